// round 9
// baseline (speedup 1.0000x reference)
#include <cuda_runtime.h>
#include <math.h>

// Problem constants
#define TSTEPS 199
#define TTOT   200
#define BSZ    256
#define HD     512
#define BH     (BSZ*HD)        // 131072
#define DIN    64
#define DOUT   64
#define NCLS   10
#define LIPC   0.909f

#define ACT_NONE 0
#define ACT_LIP  1

// ---------------- scratch (static device globals; no allocation) ----------------
__device__ float g_P[TSTEPS*BH];            // folded x-path bias per (t,b,h)  ~104MB
__device__ float g_Z[TTOT*BH];              // trajectory z[t][b][h]           ~105MB
__device__ float g_predtmp[TTOT*BSZ*DOUT];  // decode in (t,b) order            ~13MB
__device__ float g_h[BH];
__device__ float g_z3[BH];
__device__ float g_Wyf[HD*HD];              // W_emb_y @ Wf1
__device__ float g_M[DIN*HD];               // W_X @ W_emb_x @ Wf1
__device__ float g_M2[DIN*HD];              // W_X @ W_emb_x
__device__ float g_tt[TSTEPS*HD];
__device__ float g_G1[TSTEPS*HD];
__device__ float g_gt[TSTEPS*HD];
__device__ float g_cvec[HD];
__device__ float g_tmpvec[HD];
__device__ float g_dts[TSTEPS];
__device__ float g_sqdts[TSTEPS];
__device__ int   g_lastidx[BSZ];

__device__ __forceinline__ float lipswish(float x) {
    return LIPC * x / (1.0f + __expf(-x));
}

// ---------------- prep: tt, dts, sqrt(dts), last_idx ----------------
__global__ void prep_kernel(const float* __restrict__ times,
                            const float* __restrict__ W_noise,
                            const float* __restrict__ b_noise,
                            const int*   __restrict__ mask)
{
    int idx = blockIdx.x * blockDim.x + threadIdx.x;
    if (idx < TSTEPS * HD) {
        int t = idx >> 9, h = idx & (HD - 1);
        g_tt[idx] = times[t] * W_noise[h] + b_noise[h];
    }
    if (idx < TSTEPS) {
        float d = times[idx + 1] - times[idx];
        g_dts[idx] = d;
        g_sqdts[idx] = sqrtf(d);
    }
    if (idx < BSZ) {
        int s = 0;
        for (int t = 0; t < TTOT; t++) s += mask[idx * TTOT + t];
        int li = s - 1;
        if (li < 0) li = 0;
        if (li > TTOT - 1) li = TTOT - 1;
        g_lastidx[idx] = li;
    }
}

// ---------------- generic fp32 GEMM: C = act(A@B + bias) ----------------
// A: MxK (lda), B: KxN (ldb), bias: per-col vector (stride 0) or full matrix
// (stride = ldc), may be null. 32x32 tile, BK=32, 256 threads, 2x2 micro-tile.
__global__ void gemm_generic(const float* __restrict__ A, int lda,
                             const float* __restrict__ B, int ldb,
                             const float* __restrict__ bias, int bias_stride,
                             float* __restrict__ C, int ldc,
                             int M, int N, int K, int act)
{
    __shared__ float As[32][33];
    __shared__ float Bs[32][33];
    int tid = threadIdx.x;
    int tx = tid & 15, ty = tid >> 4;
    int rowBase = blockIdx.y * 32;
    int colBase = blockIdx.x * 32;

    float acc00 = 0.f, acc01 = 0.f, acc10 = 0.f, acc11 = 0.f;

    for (int k0 = 0; k0 < K; k0 += 32) {
        #pragma unroll
        for (int i = 0; i < 4; i++) {
            int idx = tid + i * 256;
            int r = idx >> 5, c = idx & 31;
            int ar = rowBase + r, ac = k0 + c;
            As[r][c] = (ar < M && ac < K) ? A[(size_t)ar * lda + ac] : 0.f;
            int br = k0 + r, bc = colBase + c;
            Bs[r][c] = (br < K && bc < N) ? B[(size_t)br * ldb + bc] : 0.f;
        }
        __syncthreads();
        #pragma unroll
        for (int kk = 0; kk < 32; kk++) {
            float a0 = As[ty][kk], a1 = As[ty + 16][kk];
            float b0 = Bs[kk][tx], b1 = Bs[kk][tx + 16];
            acc00 = fmaf(a0, b0, acc00);
            acc01 = fmaf(a0, b1, acc01);
            acc10 = fmaf(a1, b0, acc10);
            acc11 = fmaf(a1, b1, acc11);
        }
        __syncthreads();
    }

    int r0 = rowBase + ty, r1 = r0 + 16;
    int c0 = colBase + tx, c1 = c0 + 16;

    #pragma unroll
    for (int i = 0; i < 4; i++) {
        int r = (i & 2) ? r1 : r0;
        int c = (i & 1) ? c1 : c0;
        float v = (i == 0) ? acc00 : (i == 1) ? acc01 : (i == 2) ? acc10 : acc11;
        if (r < M && c < N) {
            if (bias) v += bias[(size_t)r * bias_stride + c];
            if (act == ACT_LIP) v = lipswish(v);
            C[(size_t)r * ldc + c] = v;
        }
    }
}

// ---------------- P precompute: P[t][b][n] = a[b,t,:] @ g_M + cvec[n] --------
// grid: (n-tiles 8, b-tiles 8, t 199), 256 threads; BM=32 (b), BN=64 (n), K=64
__global__ void kernel_P(const float* __restrict__ coeffs)
{
    __shared__ float As[32][65];  // [b][d]
    __shared__ float Bs[64][65];  // [d][n]
    int t  = blockIdx.z;
    int b0 = blockIdx.y * 32;
    int n0 = blockIdx.x * 64;
    int tid = threadIdx.x;

    #pragma unroll
    for (int i = 0; i < 8; i++) {
        int idx = tid + i * 256;
        int r = idx >> 6, c = idx & 63;
        As[r][c] = coeffs[((size_t)(b0 + r) * TSTEPS + t) * 256 + c]; // a-part: d<64
    }
    #pragma unroll
    for (int i = 0; i < 16; i++) {
        int idx = tid + i * 256;
        int r = idx >> 6, c = idx & 63;
        Bs[r][c] = g_M[r * HD + n0 + c];
    }
    __syncthreads();

    int tx = tid & 15, ty = tid >> 4;  // rows {ty, ty+16}, cols tx*4..tx*4+3
    float acc[2][4] = {};
    #pragma unroll
    for (int k = 0; k < 64; k++) {
        float a0 = As[ty][k], a1 = As[ty + 16][k];
        #pragma unroll
        for (int j = 0; j < 4; j++) {
            float b = Bs[k][tx * 4 + j];
            acc[0][j] = fmaf(a0, b, acc[0][j]);
            acc[1][j] = fmaf(a1, b, acc[1][j]);
        }
    }
    #pragma unroll
    for (int ri = 0; ri < 2; ri++) {
        int r = b0 + ty + ri * 16;
        #pragma unroll
        for (int j = 0; j < 4; j++) {
            int c = n0 + tx * 4 + j;
            g_P[(size_t)t * BH + (size_t)r * HD + c] = acc[ri][j] + g_cvec[c];
        }
    }
}

// ---------------- step K3: u = z3 @ W_out;  y_{t+1} = y_t + (u+b_out)*dt + dW -
__global__ void step_k3_kernel(int t,
                               const float* __restrict__ noise,
                               const float* __restrict__ W_out,
                               const float* __restrict__ b_out)
{
    __shared__ float As[32][33];
    __shared__ float Bs[32][33];
    int tid = threadIdx.x;
    int tx = tid & 15, ty = tid >> 4;
    int rowBase = blockIdx.y * 32;
    int colBase = blockIdx.x * 32;

    float acc00 = 0.f, acc01 = 0.f, acc10 = 0.f, acc11 = 0.f;

    for (int k0 = 0; k0 < HD; k0 += 32) {
        #pragma unroll
        for (int i = 0; i < 4; i++) {
            int idx = tid + i * 256;
            int r = idx >> 5, c = idx & 31;
            As[r][c] = g_z3[(size_t)(rowBase + r) * HD + k0 + c];
            Bs[r][c] = W_out[(size_t)(k0 + r) * HD + colBase + c];
        }
        __syncthreads();
        #pragma unroll
        for (int kk = 0; kk < 32; kk++) {
            float a0 = As[ty][kk], a1 = As[ty + 16][kk];
            float b0 = Bs[kk][tx], b1 = Bs[kk][tx + 16];
            acc00 = fmaf(a0, b0, acc00);
            acc01 = fmaf(a0, b1, acc01);
            acc10 = fmaf(a1, b0, acc10);
            acc11 = fmaf(a1, b1, acc11);
        }
        __syncthreads();
    }

    float dt = g_dts[t], sq = g_sqdts[t];
    const float* Zt = g_Z + (size_t)t * BH;
    float*       Zn = g_Z + (size_t)(t + 1) * BH;

    int r0 = rowBase + ty, r1 = r0 + 16;
    int c0 = colBase + tx, c1 = c0 + 16;

    #pragma unroll
    for (int i = 0; i < 4; i++) {
        int r = (i & 2) ? r1 : r0;
        int c = (i & 1) ? c1 : c0;
        float u = (i == 0) ? acc00 : (i == 1) ? acc01 : (i == 2) ? acc10 : acc11;
        float dwv = g_gt[t * HD + c] * noise[((size_t)t * BSZ + r) * HD + c] * sq;
        Zn[(size_t)r * HD + c] = Zt[(size_t)r * HD + c] + (u + b_out[c]) * dt + dwv;
    }
}

// ---------------- reorder decode output (t,b,d) -> (b,t,d) ----------------
__global__ void reorder_kernel(float* __restrict__ out)
{
    int idx = blockIdx.x * blockDim.x + threadIdx.x;
    if (idx < TTOT * BSZ * DOUT) {
        int d = idx & 63;
        int r = idx >> 6;         // r = t*BSZ + b
        int tpos = r >> 8;        // /256
        int b = r & 255;
        out[((size_t)b * TTOT + tpos) * DOUT + d] = g_predtmp[idx];
    }
}

// ---------------- classifier: logits = z[last_idx] @ W_cls + b_cls ----------
__global__ void cls_kernel(const float* __restrict__ W_cls,
                           const float* __restrict__ b_cls,
                           float* __restrict__ logits)
{
    int b = blockIdx.x;
    int w = threadIdx.x >> 5, lane = threadIdx.x & 31;
    if (w >= NCLS) return;
    int li = g_lastidx[b];
    const float* z = g_Z + ((size_t)li * BSZ + b) * HD;
    float s = 0.f;
    for (int h = lane; h < HD; h += 32)
        s += z[h] * W_cls[h * NCLS + w];
    #pragma unroll
    for (int o = 16; o; o >>= 1) s += __shfl_down_sync(0xffffffffu, s, o);
    if (lane == 0) logits[b * NCLS + w] = s + b_cls[w];
}

// ---------------- launch ----------------
extern "C" void kernel_launch(void* const* d_in, const int* in_sizes, int n_in,
                              void* d_out, int out_size)
{
    const float* coeffs  = (const float*)d_in[0];
    const float* times   = (const float*)d_in[1];
    const float* noise   = (const float*)d_in[2];
    const float* W_X     = (const float*)d_in[3];
    const float* b_X     = (const float*)d_in[4];
    const float* W_emb   = (const float*)d_in[5];
    const float* b_emb   = (const float*)d_in[6];
    const float* Wf1     = (const float*)d_in[7];
    const float* bf1     = (const float*)d_in[8];
    const float* Wf2     = (const float*)d_in[9];
    const float* bf2     = (const float*)d_in[10];
    const float* W_out   = (const float*)d_in[11];
    const float* b_out   = (const float*)d_in[12];
    const float* W_noise = (const float*)d_in[13];
    const float* b_noise = (const float*)d_in[14];
    const float* Wg1     = (const float*)d_in[15];
    const float* bg1     = (const float*)d_in[16];
    const float* Wg2     = (const float*)d_in[17];
    const float* bg2     = (const float*)d_in[18];
    const float* W_init  = (const float*)d_in[19];
    const float* b_init  = (const float*)d_in[20];
    const float* W_dec   = (const float*)d_in[21];
    const float* b_dec   = (const float*)d_in[22];
    const float* W_cls   = (const float*)d_in[23];
    const float* b_cls   = (const float*)d_in[24];
    const int*   mask    = (const int*)  d_in[25];
    float* out = (float*)d_out;

    // resolve device-symbol addresses (host-side API, not a stream op)
    float *pP, *pZ, *pPred, *pH, *pZ3, *pWyf, *pM, *pM2, *pTT, *pG1, *pGT, *pCvec, *pTmpv;
    cudaGetSymbolAddress((void**)&pP,    g_P);
    cudaGetSymbolAddress((void**)&pZ,    g_Z);
    cudaGetSymbolAddress((void**)&pPred, g_predtmp);
    cudaGetSymbolAddress((void**)&pH,    g_h);
    cudaGetSymbolAddress((void**)&pZ3,   g_z3);
    cudaGetSymbolAddress((void**)&pWyf,  g_Wyf);
    cudaGetSymbolAddress((void**)&pM,    g_M);
    cudaGetSymbolAddress((void**)&pM2,   g_M2);
    cudaGetSymbolAddress((void**)&pTT,   g_tt);
    cudaGetSymbolAddress((void**)&pG1,   g_G1);
    cudaGetSymbolAddress((void**)&pGT,   g_gt);
    cudaGetSymbolAddress((void**)&pCvec, g_cvec);
    cudaGetSymbolAddress((void**)&pTmpv, g_tmpvec);

    // 1. prep: tt, dts, sqrt(dts), last_idx
    prep_kernel<<<(TSTEPS * HD + 255) / 256, 256>>>(times, W_noise, b_noise, mask);

    // 2. diffusion path: G1 = lipswish(tt@Wg1+bg1); gt = G1@Wg2+bg2
    gemm_generic<<<dim3(16, 7), 256>>>(pTT, HD, Wg1, HD, bg1, 0, pG1, HD,
                                       TSTEPS, HD, HD, ACT_LIP);
    gemm_generic<<<dim3(16, 7), 256>>>(pG1, HD, Wg2, HD, bg2, 0, pGT, HD,
                                       TSTEPS, HD, HD, ACT_NONE);

    // 3. weight folds
    //    M2 = W_X @ W_emb_x ;  M = M2 @ Wf1
    gemm_generic<<<dim3(16, 2), 256>>>(W_X, HD, W_emb + HD * HD, HD, nullptr, 0,
                                       pM2, HD, DIN, HD, HD, ACT_NONE);
    gemm_generic<<<dim3(16, 2), 256>>>(pM2, HD, Wf1, HD, nullptr, 0,
                                       pM, HD, DIN, HD, HD, ACT_NONE);
    //    tmpvec = b_X @ W_emb_x + b_emb ;  cvec = tmpvec @ Wf1 + bf1
    gemm_generic<<<dim3(16, 1), 256>>>(b_X, HD, W_emb + HD * HD, HD, b_emb, 0,
                                       pTmpv, HD, 1, HD, HD, ACT_NONE);
    gemm_generic<<<dim3(16, 1), 256>>>(pTmpv, HD, Wf1, HD, bf1, 0,
                                       pCvec, HD, 1, HD, HD, ACT_NONE);
    //    Wyf = W_emb_y @ Wf1
    gemm_generic<<<dim3(16, 16), 256>>>(W_emb, HD, Wf1, HD, nullptr, 0,
                                        pWyf, HD, HD, HD, HD, ACT_NONE);

    // 4. y0 = a[:,0,:] @ W_init + b_init  (A = coeffs with lda = 199*256)
    gemm_generic<<<dim3(16, 8), 256>>>(coeffs, TSTEPS * 256, W_init, HD, b_init, 0,
                                       pZ, HD, BSZ, HD, DIN, ACT_NONE);

    // 5. P[t] = a[:,t,:] @ M + cvec  (fully parallel over t)
    kernel_P<<<dim3(8, 8, TSTEPS), 256>>>(coeffs);

    // 6. sequential scan: 199 steps x 3 dependent GEMMs
    for (int t = 0; t < TSTEPS; t++) {
        // h = lipswish(y @ Wyf + P[t])
        gemm_generic<<<dim3(16, 8), 256>>>(pZ + (size_t)t * BH, HD, pWyf, HD,
                                           pP + (size_t)t * BH, HD,
                                           pH, HD, BSZ, HD, HD, ACT_LIP);
        // z3 = h @ Wf2 + bf2
        gemm_generic<<<dim3(16, 8), 256>>>(pH, HD, Wf2, HD, bf2, 0,
                                           pZ3, HD, BSZ, HD, HD, ACT_NONE);
        // y_{t+1} = y_t + (z3@W_out + b_out)*dt + gt*noise*sqrt(dt)
        step_k3_kernel<<<dim3(16, 8), 256>>>(t, noise, W_out, b_out);
    }

    // 7. decode: predtmp[(t,b),d] = Z @ W_dec + b_dec, then reorder to (b,t,d)
    gemm_generic<<<dim3(2, 1600), 256>>>(pZ, HD, W_dec, DOUT, b_dec, 0,
                                         pPred, DOUT, TTOT * BSZ, DOUT, HD, ACT_NONE);
    reorder_kernel<<<(TTOT * BSZ * DOUT + 255) / 256, 256>>>(out);

    // 8. classifier logits
    cls_kernel<<<BSZ, 320>>>(W_cls, b_cls, out + (size_t)TTOT * BSZ * DOUT);
}

// round 10
// speedup vs baseline: 1.7183x; 1.7183x over previous
#include <cuda_runtime.h>
#include <math.h>

// Problem constants
#define TSTEPS 199
#define TTOT   200
#define BSZ    256
#define HD     512
#define BH     (BSZ*HD)        // 131072
#define DIN    64
#define DOUT   64
#define NCLS   10
#define LIPC   0.909f

#define ACT_NONE 0
#define ACT_LIP  1

#define RG         8    // row groups (32 rows each)
#define GROUP_CTAS 16   // col CTAs per group (32 cols each)

// ---------------- scratch (static device globals; no allocation) ----------------
__device__ __align__(256) float g_P[TSTEPS*BH];            // folded x-path bias  ~104MB
__device__ __align__(256) float g_Z[TTOT*BH];              // trajectory          ~105MB
__device__ __align__(256) float g_predtmp[TTOT*BSZ*DOUT];  // decode (t,b) order
__device__ __align__(256) float g_h[BH];
__device__ __align__(256) float g_Wyf[HD*HD];              // W_emb_y @ Wf1
__device__ __align__(256) float g_W2o[HD*HD];              // Wf2 @ W_out (fold)
__device__ __align__(256) float g_b2o[HD];                 // bf2 @ W_out + b_out
__device__ __align__(256) float g_M[DIN*HD];               // W_X @ W_emb_x @ Wf1
__device__ __align__(256) float g_M2[DIN*HD];
__device__ __align__(256) float g_tt[TSTEPS*HD];
__device__ __align__(256) float g_G1[TSTEPS*HD];
__device__ __align__(256) float g_gt[TSTEPS*HD];
__device__ __align__(256) float g_cvec[HD];
__device__ __align__(256) float g_tmpvec[HD];
__device__ float g_dts[TSTEPS];
__device__ float g_sqdts[TSTEPS];
__device__ int   g_lastidx[BSZ];
__device__ unsigned g_barctr[RG];

__device__ __forceinline__ float lipswish(float x) {
    return LIPC * x / (1.0f + __expf(-x));
}

// ---------------- prep: tt, dts, sqrt(dts), last_idx, barrier counters -------
__global__ void prep_kernel(const float* __restrict__ times,
                            const float* __restrict__ W_noise,
                            const float* __restrict__ b_noise,
                            const int*   __restrict__ mask)
{
    int idx = blockIdx.x * blockDim.x + threadIdx.x;
    if (idx < TSTEPS * HD) {
        int t = idx >> 9, h = idx & (HD - 1);
        g_tt[idx] = times[t] * W_noise[h] + b_noise[h];
    }
    if (idx < TSTEPS) {
        float d = times[idx + 1] - times[idx];
        g_dts[idx] = d;
        g_sqdts[idx] = sqrtf(d);
    }
    if (idx < BSZ) {
        int s = 0;
        for (int t = 0; t < TTOT; t++) s += mask[idx * TTOT + t];
        int li = s - 1;
        if (li < 0) li = 0;
        if (li > TTOT - 1) li = TTOT - 1;
        g_lastidx[idx] = li;
    }
    if (idx < RG) g_barctr[idx] = 0u;   // reset group barriers every replay
}

// ---------------- generic fp32 GEMM: C = act(A@B + bias) ----------------
__global__ void gemm_generic(const float* __restrict__ A, int lda,
                             const float* __restrict__ B, int ldb,
                             const float* __restrict__ bias, int bias_stride,
                             float* __restrict__ C, int ldc,
                             int M, int N, int K, int act)
{
    __shared__ float As[32][33];
    __shared__ float Bs[32][33];
    int tid = threadIdx.x;
    int tx = tid & 15, ty = tid >> 4;
    int rowBase = blockIdx.y * 32;
    int colBase = blockIdx.x * 32;

    float acc00 = 0.f, acc01 = 0.f, acc10 = 0.f, acc11 = 0.f;

    for (int k0 = 0; k0 < K; k0 += 32) {
        #pragma unroll
        for (int i = 0; i < 4; i++) {
            int idx = tid + i * 256;
            int r = idx >> 5, c = idx & 31;
            int ar = rowBase + r, ac = k0 + c;
            As[r][c] = (ar < M && ac < K) ? A[(size_t)ar * lda + ac] : 0.f;
            int br = k0 + r, bc = colBase + c;
            Bs[r][c] = (br < K && bc < N) ? B[(size_t)br * ldb + bc] : 0.f;
        }
        __syncthreads();
        #pragma unroll
        for (int kk = 0; kk < 32; kk++) {
            float a0 = As[ty][kk], a1 = As[ty + 16][kk];
            float b0 = Bs[kk][tx], b1 = Bs[kk][tx + 16];
            acc00 = fmaf(a0, b0, acc00);
            acc01 = fmaf(a0, b1, acc01);
            acc10 = fmaf(a1, b0, acc10);
            acc11 = fmaf(a1, b1, acc11);
        }
        __syncthreads();
    }

    int r0 = rowBase + ty, r1 = r0 + 16;
    int c0 = colBase + tx, c1 = c0 + 16;

    #pragma unroll
    for (int i = 0; i < 4; i++) {
        int r = (i & 2) ? r1 : r0;
        int c = (i & 1) ? c1 : c0;
        float v = (i == 0) ? acc00 : (i == 1) ? acc01 : (i == 2) ? acc10 : acc11;
        if (r < M && c < N) {
            if (bias) v += bias[(size_t)r * bias_stride + c];
            if (act == ACT_LIP) v = lipswish(v);
            C[(size_t)r * ldc + c] = v;
        }
    }
}

// ---------------- P precompute: P[t][b][n] = a[b,t,:] @ g_M + cvec[n] --------
__global__ void kernel_P(const float* __restrict__ coeffs)
{
    __shared__ float As[32][65];  // [b][d]
    __shared__ float Bs[64][65];  // [d][n]
    int t  = blockIdx.z;
    int b0 = blockIdx.y * 32;
    int n0 = blockIdx.x * 64;
    int tid = threadIdx.x;

    #pragma unroll
    for (int i = 0; i < 8; i++) {
        int idx = tid + i * 256;
        int r = idx >> 6, c = idx & 63;
        As[r][c] = coeffs[((size_t)(b0 + r) * TSTEPS + t) * 256 + c]; // a-part
    }
    #pragma unroll
    for (int i = 0; i < 16; i++) {
        int idx = tid + i * 256;
        int r = idx >> 6, c = idx & 63;
        Bs[r][c] = g_M[r * HD + n0 + c];
    }
    __syncthreads();

    int tx = tid & 15, ty = tid >> 4;
    float acc[2][4] = {};
    #pragma unroll
    for (int k = 0; k < 64; k++) {
        float a0 = As[ty][k], a1 = As[ty + 16][k];
        #pragma unroll
        for (int j = 0; j < 4; j++) {
            float b = Bs[k][tx * 4 + j];
            acc[0][j] = fmaf(a0, b, acc[0][j]);
            acc[1][j] = fmaf(a1, b, acc[1][j]);
        }
    }
    #pragma unroll
    for (int ri = 0; ri < 2; ri++) {
        int r = b0 + ty + ri * 16;
        #pragma unroll
        for (int j = 0; j < 4; j++) {
            int c = n0 + tx * 4 + j;
            g_P[(size_t)t * BH + (size_t)r * HD + c] = acc[ri][j] + g_cvec[c];
        }
    }
}

// ---------------- group-local spin barrier (16 CTAs, all co-resident) --------
__device__ __forceinline__ void group_barrier(int g, unsigned target)
{
    __syncthreads();
    if (threadIdx.x == 0) {
        __threadfence();
        atomicAdd(&g_barctr[g], 1u);
        while (*(volatile unsigned*)&g_barctr[g] < target) __nanosleep(64);
        __threadfence();
    }
    __syncthreads();
}

// ---------------- persistent scan kernel -------------------------------------
// 128 CTAs = 8 row-groups (32 batch rows) x 16 col-CTAs (32 cols).
// Per step: h = lipswish(y @ Wyf + P[t]); y += (h @ W2o + b2o)*dt + gt*noise*sq
__global__ void __launch_bounds__(256, 1)
scan_kernel(const float* __restrict__ noise)
{
    __shared__ float As[2][32][36];
    __shared__ float Bs[2][32][36];

    const int g   = blockIdx.x >> 4;
    const int c0  = (blockIdx.x & 15) << 5;
    const int r0  = g << 5;
    const int tid = threadIdx.x;
    const int lr  = tid >> 3;            // 0..31  (tile row for loads)
    const int lc4 = (tid & 7) << 2;      // 0..28  (float4 col offset)
    const int tx  = tid & 15, ty = tid >> 4;

    unsigned target = GROUP_CTAS;

    for (int t = 0; t < TSTEPS; t++) {
        const float* Zt = g_Z + (size_t)t * BH;
        float*       Zn = g_Z + (size_t)(t + 1) * BH;

        // ================= GEMM1: h = lip(Zt @ Wyf + P[t]) =================
        {
            const float* Abase = Zt + (size_t)r0 * HD;
            const float* Bbase = g_Wyf + c0;
            float a00 = 0.f, a01 = 0.f, a10 = 0.f, a11 = 0.f;

            float4 av = *(const float4*)(Abase + (size_t)lr * HD + lc4);
            float4 bv = *(const float4*)(Bbase + (size_t)lr * HD + lc4);
            *(float4*)&As[0][lr][lc4] = av;
            *(float4*)&Bs[0][lr][lc4] = bv;
            __syncthreads();

            #pragma unroll 2
            for (int kt = 0; kt < 16; kt++) {
                const int cur = kt & 1;
                if (kt < 15) {
                    const int k0 = (kt + 1) << 5;
                    av = *(const float4*)(Abase + (size_t)lr * HD + k0 + lc4);
                    bv = *(const float4*)(Bbase + (size_t)(k0 + lr) * HD + lc4);
                }
                #pragma unroll
                for (int kk = 0; kk < 32; kk++) {
                    float x0 = As[cur][ty][kk];
                    float x1 = As[cur][ty + 16][kk];
                    float w0 = Bs[cur][kk][tx];
                    float w1 = Bs[cur][kk][tx + 16];
                    a00 = fmaf(x0, w0, a00); a01 = fmaf(x0, w1, a01);
                    a10 = fmaf(x1, w0, a10); a11 = fmaf(x1, w1, a11);
                }
                if (kt < 15) {
                    const int nxt = (kt + 1) & 1;
                    *(float4*)&As[nxt][lr][lc4] = av;
                    *(float4*)&Bs[nxt][lr][lc4] = bv;
                    __syncthreads();
                }
            }
            const float* Pt = g_P + (size_t)t * BH;
            const int ra = r0 + ty, rb = ra + 16;
            const int ca = c0 + tx, cb = ca + 16;
            g_h[(size_t)ra * HD + ca] = lipswish(a00 + Pt[(size_t)ra * HD + ca]);
            g_h[(size_t)ra * HD + cb] = lipswish(a01 + Pt[(size_t)ra * HD + cb]);
            g_h[(size_t)rb * HD + ca] = lipswish(a10 + Pt[(size_t)rb * HD + ca]);
            g_h[(size_t)rb * HD + cb] = lipswish(a11 + Pt[(size_t)rb * HD + cb]);
        }
        group_barrier(g, target); target += GROUP_CTAS;

        // ====== GEMM2: y_{t+1} = y + (h @ W2o + b2o)*dt + gt*noise*sq ======
        {
            const float* Abase = g_h + (size_t)r0 * HD;
            const float* Bbase = g_W2o + c0;
            float a00 = 0.f, a01 = 0.f, a10 = 0.f, a11 = 0.f;

            float4 av = *(const float4*)(Abase + (size_t)lr * HD + lc4);
            float4 bv = *(const float4*)(Bbase + (size_t)lr * HD + lc4);
            *(float4*)&As[0][lr][lc4] = av;
            *(float4*)&Bs[0][lr][lc4] = bv;
            __syncthreads();

            #pragma unroll 2
            for (int kt = 0; kt < 16; kt++) {
                const int cur = kt & 1;
                if (kt < 15) {
                    const int k0 = (kt + 1) << 5;
                    av = *(const float4*)(Abase + (size_t)lr * HD + k0 + lc4);
                    bv = *(const float4*)(Bbase + (size_t)(k0 + lr) * HD + lc4);
                }
                #pragma unroll
                for (int kk = 0; kk < 32; kk++) {
                    float x0 = As[cur][ty][kk];
                    float x1 = As[cur][ty + 16][kk];
                    float w0 = Bs[cur][kk][tx];
                    float w1 = Bs[cur][kk][tx + 16];
                    a00 = fmaf(x0, w0, a00); a01 = fmaf(x0, w1, a01);
                    a10 = fmaf(x1, w0, a10); a11 = fmaf(x1, w1, a11);
                }
                if (kt < 15) {
                    const int nxt = (kt + 1) & 1;
                    *(float4*)&As[nxt][lr][lc4] = av;
                    *(float4*)&Bs[nxt][lr][lc4] = bv;
                    __syncthreads();
                }
            }
            const float dt = g_dts[t], sq = g_sqdts[t];
            const float* Nt = noise + (size_t)t * BH;
            const int ra = r0 + ty, rb = ra + 16;
            const int ca = c0 + tx, cb = ca + 16;

            float dwa = g_gt[t * HD + ca] * sq;
            float dwb = g_gt[t * HD + cb] * sq;
            float boa = g_b2o[ca], bob = g_b2o[cb];

            Zn[(size_t)ra * HD + ca] = Zt[(size_t)ra * HD + ca]
                + (a00 + boa) * dt + dwa * Nt[(size_t)ra * HD + ca];
            Zn[(size_t)ra * HD + cb] = Zt[(size_t)ra * HD + cb]
                + (a01 + bob) * dt + dwb * Nt[(size_t)ra * HD + cb];
            Zn[(size_t)rb * HD + ca] = Zt[(size_t)rb * HD + ca]
                + (a10 + boa) * dt + dwa * Nt[(size_t)rb * HD + ca];
            Zn[(size_t)rb * HD + cb] = Zt[(size_t)rb * HD + cb]
                + (a11 + bob) * dt + dwb * Nt[(size_t)rb * HD + cb];
        }
        group_barrier(g, target); target += GROUP_CTAS;
    }
}

// ---------------- reorder decode output (t,b,d) -> (b,t,d) ----------------
__global__ void reorder_kernel(float* __restrict__ out)
{
    int idx = blockIdx.x * blockDim.x + threadIdx.x;
    if (idx < TTOT * BSZ * DOUT) {
        int d = idx & 63;
        int r = idx >> 6;         // r = t*BSZ + b
        int tpos = r >> 8;
        int b = r & 255;
        out[((size_t)b * TTOT + tpos) * DOUT + d] = g_predtmp[idx];
    }
}

// ---------------- classifier: logits = z[last_idx] @ W_cls + b_cls ----------
__global__ void cls_kernel(const float* __restrict__ W_cls,
                           const float* __restrict__ b_cls,
                           float* __restrict__ logits)
{
    int b = blockIdx.x;
    int w = threadIdx.x >> 5, lane = threadIdx.x & 31;
    if (w >= NCLS) return;
    int li = g_lastidx[b];
    const float* z = g_Z + ((size_t)li * BSZ + b) * HD;
    float s = 0.f;
    for (int h = lane; h < HD; h += 32)
        s += z[h] * W_cls[h * NCLS + w];
    #pragma unroll
    for (int o = 16; o; o >>= 1) s += __shfl_down_sync(0xffffffffu, s, o);
    if (lane == 0) logits[b * NCLS + w] = s + b_cls[w];
}

// ---------------- launch ----------------
extern "C" void kernel_launch(void* const* d_in, const int* in_sizes, int n_in,
                              void* d_out, int out_size)
{
    const float* coeffs  = (const float*)d_in[0];
    const float* times   = (const float*)d_in[1];
    const float* noise   = (const float*)d_in[2];
    const float* W_X     = (const float*)d_in[3];
    const float* b_X     = (const float*)d_in[4];
    const float* W_emb   = (const float*)d_in[5];
    const float* b_emb   = (const float*)d_in[6];
    const float* Wf1     = (const float*)d_in[7];
    const float* bf1     = (const float*)d_in[8];
    const float* Wf2     = (const float*)d_in[9];
    const float* bf2     = (const float*)d_in[10];
    const float* W_out   = (const float*)d_in[11];
    const float* b_out   = (const float*)d_in[12];
    const float* W_noise = (const float*)d_in[13];
    const float* b_noise = (const float*)d_in[14];
    const float* Wg1     = (const float*)d_in[15];
    const float* bg1     = (const float*)d_in[16];
    const float* Wg2     = (const float*)d_in[17];
    const float* bg2     = (const float*)d_in[18];
    const float* W_init  = (const float*)d_in[19];
    const float* b_init  = (const float*)d_in[20];
    const float* W_dec   = (const float*)d_in[21];
    const float* b_dec   = (const float*)d_in[22];
    const float* W_cls   = (const float*)d_in[23];
    const float* b_cls   = (const float*)d_in[24];
    const int*   mask    = (const int*)  d_in[25];
    float* out = (float*)d_out;

    float *pP, *pZ, *pPred, *pWyf, *pW2o, *pB2o, *pM, *pM2,
          *pTT, *pG1, *pGT, *pCvec, *pTmpv;
    cudaGetSymbolAddress((void**)&pP,    g_P);
    cudaGetSymbolAddress((void**)&pZ,    g_Z);
    cudaGetSymbolAddress((void**)&pPred, g_predtmp);
    cudaGetSymbolAddress((void**)&pWyf,  g_Wyf);
    cudaGetSymbolAddress((void**)&pW2o,  g_W2o);
    cudaGetSymbolAddress((void**)&pB2o,  g_b2o);
    cudaGetSymbolAddress((void**)&pM,    g_M);
    cudaGetSymbolAddress((void**)&pM2,   g_M2);
    cudaGetSymbolAddress((void**)&pTT,   g_tt);
    cudaGetSymbolAddress((void**)&pG1,   g_G1);
    cudaGetSymbolAddress((void**)&pGT,   g_gt);
    cudaGetSymbolAddress((void**)&pCvec, g_cvec);
    cudaGetSymbolAddress((void**)&pTmpv, g_tmpvec);

    // 1. prep: tt, dts, sqrt(dts), last_idx, barrier reset
    prep_kernel<<<(TSTEPS * HD + 255) / 256, 256>>>(times, W_noise, b_noise, mask);

    // 2. diffusion path: G1 = lipswish(tt@Wg1+bg1); gt = G1@Wg2+bg2
    gemm_generic<<<dim3(16, 7), 256>>>(pTT, HD, Wg1, HD, bg1, 0, pG1, HD,
                                       TSTEPS, HD, HD, ACT_LIP);
    gemm_generic<<<dim3(16, 7), 256>>>(pG1, HD, Wg2, HD, bg2, 0, pGT, HD,
                                       TSTEPS, HD, HD, ACT_NONE);

    // 3. weight folds
    gemm_generic<<<dim3(16, 2), 256>>>(W_X, HD, W_emb + HD * HD, HD, nullptr, 0,
                                       pM2, HD, DIN, HD, HD, ACT_NONE);
    gemm_generic<<<dim3(16, 2), 256>>>(pM2, HD, Wf1, HD, nullptr, 0,
                                       pM, HD, DIN, HD, HD, ACT_NONE);
    gemm_generic<<<dim3(16, 1), 256>>>(b_X, HD, W_emb + HD * HD, HD, b_emb, 0,
                                       pTmpv, HD, 1, HD, HD, ACT_NONE);
    gemm_generic<<<dim3(16, 1), 256>>>(pTmpv, HD, Wf1, HD, bf1, 0,
                                       pCvec, HD, 1, HD, HD, ACT_NONE);
    gemm_generic<<<dim3(16, 16), 256>>>(W_emb, HD, Wf1, HD, nullptr, 0,
                                        pWyf, HD, HD, HD, HD, ACT_NONE);
    //    W2o = Wf2 @ W_out ;  b2o = bf2 @ W_out + b_out  (removes GEMM2 of scan)
    gemm_generic<<<dim3(16, 16), 256>>>(Wf2, HD, W_out, HD, nullptr, 0,
                                        pW2o, HD, HD, HD, HD, ACT_NONE);
    gemm_generic<<<dim3(16, 1), 256>>>(bf2, HD, W_out, HD, b_out, 0,
                                       pB2o, HD, 1, HD, HD, ACT_NONE);

    // 4. y0 = a[:,0,:] @ W_init + b_init
    gemm_generic<<<dim3(16, 8), 256>>>(coeffs, TSTEPS * 256, W_init, HD, b_init, 0,
                                       pZ, HD, BSZ, HD, DIN, ACT_NONE);

    // 5. P[t] = a[:,t,:] @ M + cvec  (fully parallel over t)
    kernel_P<<<dim3(8, 8, TSTEPS), 256>>>(coeffs);

    // 6. entire 199-step scan in ONE persistent kernel (128 co-resident CTAs,
    //    group-local barriers)
    scan_kernel<<<RG * GROUP_CTAS, 256>>>(noise);

    // 7. decode + reorder
    gemm_generic<<<dim3(2, 1600), 256>>>(pZ, HD, W_dec, DOUT, b_dec, 0,
                                         pPred, DOUT, TTOT * BSZ, DOUT, HD, ACT_NONE);
    reorder_kernel<<<(TTOT * BSZ * DOUT + 255) / 256, 256>>>(out);

    // 8. classifier logits
    cls_kernel<<<BSZ, 320>>>(W_cls, b_cls, out + (size_t)TTOT * BSZ * DOUT);
}

// round 11
// speedup vs baseline: 2.5271x; 1.4707x over previous
#include <cuda_runtime.h>
#include <math.h>

// Problem constants
#define TSTEPS 199
#define TTOT   200
#define BSZ    256
#define HD     512
#define BH     (BSZ*HD)        // 131072
#define DIN    64
#define DOUT   64
#define NCLS   10
#define LIPC   0.909f

#define ACT_NONE 0
#define ACT_LIP  1

#define RG         8    // row groups (32 rows each)
#define GROUP_CTAS 16   // col CTAs per group (32 cols each)

#define PAD   36                       // smem row pad (multiple of 4, conflict-free)
#define SWSZ  (HD*PAD)                 // floats per 512x32 padded buffer
#define SMEM_BYTES (3*SWSZ*4)          // Wy + Wo + A = 221184 bytes

// ---------------- scratch (static device globals; no allocation) ----------------
__device__ __align__(256) float g_P[TSTEPS*BH];            // folded x-path bias  ~104MB
__device__ __align__(256) float g_Z[TTOT*BH];              // trajectory          ~105MB
__device__ __align__(256) float g_predtmp[TTOT*BSZ*DOUT];  // decode (t,b) order
__device__ __align__(256) float g_h[BH];
__device__ __align__(256) float g_Wyf[HD*HD];              // W_emb_y @ Wf1
__device__ __align__(256) float g_W2o[HD*HD];              // Wf2 @ W_out (fold)
__device__ __align__(256) float g_b2o[HD];                 // bf2 @ W_out + b_out
__device__ __align__(256) float g_M[DIN*HD];               // W_X @ W_emb_x @ Wf1
__device__ __align__(256) float g_M2[DIN*HD];
__device__ __align__(256) float g_tt[TSTEPS*HD];
__device__ __align__(256) float g_G1[TSTEPS*HD];
__device__ __align__(256) float g_gt[TSTEPS*HD];
__device__ __align__(256) float g_cvec[HD];
__device__ __align__(256) float g_tmpvec[HD];
__device__ float g_dts[TSTEPS];
__device__ float g_sqdts[TSTEPS];
__device__ int   g_lastidx[BSZ];
__device__ unsigned g_barctr[RG];

__device__ __forceinline__ float lipswish(float x) {
    return LIPC * x / (1.0f + __expf(-x));
}

// ---------------- prep: tt, dts, sqrt(dts), last_idx, barrier counters -------
__global__ void prep_kernel(const float* __restrict__ times,
                            const float* __restrict__ W_noise,
                            const float* __restrict__ b_noise,
                            const int*   __restrict__ mask)
{
    int idx = blockIdx.x * blockDim.x + threadIdx.x;
    if (idx < TSTEPS * HD) {
        int t = idx >> 9, h = idx & (HD - 1);
        g_tt[idx] = times[t] * W_noise[h] + b_noise[h];
    }
    if (idx < TSTEPS) {
        float d = times[idx + 1] - times[idx];
        g_dts[idx] = d;
        g_sqdts[idx] = sqrtf(d);
    }
    if (idx < BSZ) {
        int s = 0;
        for (int t = 0; t < TTOT; t++) s += mask[idx * TTOT + t];
        int li = s - 1;
        if (li < 0) li = 0;
        if (li > TTOT - 1) li = TTOT - 1;
        g_lastidx[idx] = li;
    }
    if (idx < RG) g_barctr[idx] = 0u;   // reset group barriers every replay
}

// ---------------- generic fp32 GEMM: C = act(A@B + bias) ----------------
__global__ void gemm_generic(const float* __restrict__ A, int lda,
                             const float* __restrict__ B, int ldb,
                             const float* __restrict__ bias, int bias_stride,
                             float* __restrict__ C, int ldc,
                             int M, int N, int K, int act)
{
    __shared__ float As[32][33];
    __shared__ float Bs[32][33];
    int tid = threadIdx.x;
    int tx = tid & 15, ty = tid >> 4;
    int rowBase = blockIdx.y * 32;
    int colBase = blockIdx.x * 32;

    float acc00 = 0.f, acc01 = 0.f, acc10 = 0.f, acc11 = 0.f;

    for (int k0 = 0; k0 < K; k0 += 32) {
        #pragma unroll
        for (int i = 0; i < 4; i++) {
            int idx = tid + i * 256;
            int r = idx >> 5, c = idx & 31;
            int ar = rowBase + r, ac = k0 + c;
            As[r][c] = (ar < M && ac < K) ? A[(size_t)ar * lda + ac] : 0.f;
            int br = k0 + r, bc = colBase + c;
            Bs[r][c] = (br < K && bc < N) ? B[(size_t)br * ldb + bc] : 0.f;
        }
        __syncthreads();
        #pragma unroll
        for (int kk = 0; kk < 32; kk++) {
            float a0 = As[ty][kk], a1 = As[ty + 16][kk];
            float b0 = Bs[kk][tx], b1 = Bs[kk][tx + 16];
            acc00 = fmaf(a0, b0, acc00);
            acc01 = fmaf(a0, b1, acc01);
            acc10 = fmaf(a1, b0, acc10);
            acc11 = fmaf(a1, b1, acc11);
        }
        __syncthreads();
    }

    int r0 = rowBase + ty, r1 = r0 + 16;
    int c0 = colBase + tx, c1 = c0 + 16;

    #pragma unroll
    for (int i = 0; i < 4; i++) {
        int r = (i & 2) ? r1 : r0;
        int c = (i & 1) ? c1 : c0;
        float v = (i == 0) ? acc00 : (i == 1) ? acc01 : (i == 2) ? acc10 : acc11;
        if (r < M && c < N) {
            if (bias) v += bias[(size_t)r * bias_stride + c];
            if (act == ACT_LIP) v = lipswish(v);
            C[(size_t)r * ldc + c] = v;
        }
    }
}

// ---------------- P precompute: P[t][b][n] = a[b,t,:] @ g_M + cvec[n] --------
__global__ void kernel_P(const float* __restrict__ coeffs)
{
    __shared__ float As[32][65];  // [b][d]
    __shared__ float Bs[64][65];  // [d][n]
    int t  = blockIdx.z;
    int b0 = blockIdx.y * 32;
    int n0 = blockIdx.x * 64;
    int tid = threadIdx.x;

    #pragma unroll
    for (int i = 0; i < 8; i++) {
        int idx = tid + i * 256;
        int r = idx >> 6, c = idx & 63;
        As[r][c] = coeffs[((size_t)(b0 + r) * TSTEPS + t) * 256 + c]; // a-part
    }
    #pragma unroll
    for (int i = 0; i < 16; i++) {
        int idx = tid + i * 256;
        int r = idx >> 6, c = idx & 63;
        Bs[r][c] = g_M[r * HD + n0 + c];
    }
    __syncthreads();

    int tx = tid & 15, ty = tid >> 4;
    float acc[2][4] = {};
    #pragma unroll
    for (int k = 0; k < 64; k++) {
        float a0 = As[ty][k], a1 = As[ty + 16][k];
        #pragma unroll
        for (int j = 0; j < 4; j++) {
            float b = Bs[k][tx * 4 + j];
            acc[0][j] = fmaf(a0, b, acc[0][j]);
            acc[1][j] = fmaf(a1, b, acc[1][j]);
        }
    }
    #pragma unroll
    for (int ri = 0; ri < 2; ri++) {
        int r = b0 + ty + ri * 16;
        #pragma unroll
        for (int j = 0; j < 4; j++) {
            int c = n0 + tx * 4 + j;
            g_P[(size_t)t * BH + (size_t)r * HD + c] = acc[ri][j] + g_cvec[c];
        }
    }
}

// ---------------- group-local spin barrier (16 CTAs, all co-resident) --------
__device__ __forceinline__ void group_barrier(int g, unsigned target)
{
    __syncthreads();
    if (threadIdx.x == 0) {
        __threadfence();
        atomicAdd(&g_barctr[g], 1u);
        while (*(volatile unsigned*)&g_barctr[g] < target) __nanosleep(32);
        __threadfence();
    }
    __syncthreads();
}

// ---------------- persistent scan kernel -------------------------------------
// 128 CTAs = 8 row-groups (32 batch rows) x 16 col-CTAs (32 cols).
// Weight slices (Wyf, W2o: 512x32 each) live in smem for the whole scan.
// A tile stored k-major (transposed) for vectorized conflict-free LDS.64.
// Per step: h = lipswish(y @ Wyf + P[t]); y += (h @ W2o + b2o)*dt + gt*noise*sq
__global__ void __launch_bounds__(256, 1)
scan_kernel(const float* __restrict__ noise)
{
    extern __shared__ float smem[];
    float* sWy = smem;                 // [512][PAD]
    float* sWo = smem + SWSZ;          // [512][PAD]
    float* sA  = smem + 2 * SWSZ;      // [512][PAD]  (k-major A tile)

    const int g   = blockIdx.x >> 4;
    const int c0  = (blockIdx.x & 15) << 5;
    const int r0  = g << 5;
    const int tid = threadIdx.x;

    // compute mapping: 2x2 micro-tile
    const int row2 = (tid >> 4) << 1;         // local rows {row2, row2+1}
    const int col2 = (tid & 15) << 1;         // local cols {col2, col2+1}
    const int ra = r0 + row2, rb = ra + 1;
    const int ca = c0 + col2;                 // float2 covers (ca, ca+1)

    // loader mapping: row = lane across 32, k-chunk per warp
    const int lrow = tid & 31;
    const int wk   = tid >> 5;                // 0..7

    // ---- load persistent weight slices (once) ----
    #pragma unroll 4
    for (int it = 0; it < 64; it++) {
        int k = wk + (it << 3);
        int c = tid & 31;
        sWy[k * PAD + c] = g_Wyf[(size_t)k * HD + c0 + c];
        sWo[k * PAD + c] = g_W2o[(size_t)k * HD + c0 + c];
    }

    const float dtb2x = g_b2o[ca];
    const float dtb2y = g_b2o[ca + 1];

    unsigned target = GROUP_CTAS;

    for (int t = 0; t < TSTEPS; t++) {
        const float* Zt = g_Z + (size_t)t * BH;
        float*       Zn = g_Z + (size_t)(t + 1) * BH;

        // prefetch P[t] epilogue operands (DRAM latency hidden under k-loop)
        const float* Pt = g_P + (size_t)t * BH;
        float2 p0 = *(const float2*)(Pt + (size_t)ra * HD + ca);
        float2 p1 = *(const float2*)(Pt + (size_t)rb * HD + ca);

        // ---- load A = Zt rows (transposed into sA) ----
        {
            const float* src = Zt + (size_t)r0 * HD;
            #pragma unroll 4
            for (int it = 0; it < 16; it++) {
                int k0 = (wk + (it << 3)) << 2;
                float4 v = *(const float4*)(src + (size_t)lrow * HD + k0);
                sA[(k0 + 0) * PAD + lrow] = v.x;
                sA[(k0 + 1) * PAD + lrow] = v.y;
                sA[(k0 + 2) * PAD + lrow] = v.z;
                sA[(k0 + 3) * PAD + lrow] = v.w;
            }
        }
        __syncthreads();

        // ---- GEMM1 k-loop: acc = Zt_tile @ Wyf_slice ----
        {
            float a00 = 0.f, a01 = 0.f, a10 = 0.f, a11 = 0.f;
            #pragma unroll 8
            for (int k = 0; k < HD; k++) {
                float2 av = *(const float2*)(sA  + k * PAD + row2);
                float2 bv = *(const float2*)(sWy + k * PAD + col2);
                a00 = fmaf(av.x, bv.x, a00);
                a01 = fmaf(av.x, bv.y, a01);
                a10 = fmaf(av.y, bv.x, a10);
                a11 = fmaf(av.y, bv.y, a11);
            }
            float2 h0, h1;
            h0.x = lipswish(a00 + p0.x);
            h0.y = lipswish(a01 + p0.y);
            h1.x = lipswish(a10 + p1.x);
            h1.y = lipswish(a11 + p1.y);
            *(float2*)(g_h + (size_t)ra * HD + ca) = h0;
            *(float2*)(g_h + (size_t)rb * HD + ca) = h1;
        }
        group_barrier(g, target); target += GROUP_CTAS;

        // prefetch GEMM2 epilogue operands
        const float dt = g_dts[t], sq = g_sqdts[t];
        float2 gt2 = *(const float2*)(g_gt + t * HD + ca);
        const float* Nt = noise + (size_t)t * BH;
        float2 n0 = *(const float2*)(Nt + (size_t)ra * HD + ca);
        float2 n1 = *(const float2*)(Nt + (size_t)rb * HD + ca);
        float2 z0 = *(const float2*)(Zt + (size_t)ra * HD + ca);
        float2 z1 = *(const float2*)(Zt + (size_t)rb * HD + ca);

        // ---- load A = h rows (transposed into sA) ----
        {
            const float* src = g_h + (size_t)r0 * HD;
            #pragma unroll 4
            for (int it = 0; it < 16; it++) {
                int k0 = (wk + (it << 3)) << 2;
                float4 v = *(const float4*)(src + (size_t)lrow * HD + k0);
                sA[(k0 + 0) * PAD + lrow] = v.x;
                sA[(k0 + 1) * PAD + lrow] = v.y;
                sA[(k0 + 2) * PAD + lrow] = v.z;
                sA[(k0 + 3) * PAD + lrow] = v.w;
            }
        }
        __syncthreads();

        // ---- GEMM2 k-loop: acc = h_tile @ W2o_slice ----
        {
            float a00 = 0.f, a01 = 0.f, a10 = 0.f, a11 = 0.f;
            #pragma unroll 8
            for (int k = 0; k < HD; k++) {
                float2 av = *(const float2*)(sA  + k * PAD + row2);
                float2 bv = *(const float2*)(sWo + k * PAD + col2);
                a00 = fmaf(av.x, bv.x, a00);
                a01 = fmaf(av.x, bv.y, a01);
                a10 = fmaf(av.y, bv.x, a10);
                a11 = fmaf(av.y, bv.y, a11);
            }
            float gx = gt2.x * sq, gy = gt2.y * sq;
            float2 o0, o1;
            o0.x = z0.x + (a00 + dtb2x) * dt + gx * n0.x;
            o0.y = z0.y + (a01 + dtb2y) * dt + gy * n0.y;
            o1.x = z1.x + (a10 + dtb2x) * dt + gx * n1.x;
            o1.y = z1.y + (a11 + dtb2y) * dt + gy * n1.y;
            *(float2*)(Zn + (size_t)ra * HD + ca) = o0;
            *(float2*)(Zn + (size_t)rb * HD + ca) = o1;
        }
        group_barrier(g, target); target += GROUP_CTAS;
    }
}

// ---------------- reorder decode output (t,b,d) -> (b,t,d) ----------------
__global__ void reorder_kernel(float* __restrict__ out)
{
    int idx = blockIdx.x * blockDim.x + threadIdx.x;
    if (idx < TTOT * BSZ * DOUT) {
        int d = idx & 63;
        int r = idx >> 6;         // r = t*BSZ + b
        int tpos = r >> 8;
        int b = r & 255;
        out[((size_t)b * TTOT + tpos) * DOUT + d] = g_predtmp[idx];
    }
}

// ---------------- classifier: logits = z[last_idx] @ W_cls + b_cls ----------
__global__ void cls_kernel(const float* __restrict__ W_cls,
                           const float* __restrict__ b_cls,
                           float* __restrict__ logits)
{
    int b = blockIdx.x;
    int w = threadIdx.x >> 5, lane = threadIdx.x & 31;
    if (w >= NCLS) return;
    int li = g_lastidx[b];
    const float* z = g_Z + ((size_t)li * BSZ + b) * HD;
    float s = 0.f;
    for (int h = lane; h < HD; h += 32)
        s += z[h] * W_cls[h * NCLS + w];
    #pragma unroll
    for (int o = 16; o; o >>= 1) s += __shfl_down_sync(0xffffffffu, s, o);
    if (lane == 0) logits[b * NCLS + w] = s + b_cls[w];
}

// ---------------- launch ----------------
extern "C" void kernel_launch(void* const* d_in, const int* in_sizes, int n_in,
                              void* d_out, int out_size)
{
    const float* coeffs  = (const float*)d_in[0];
    const float* times   = (const float*)d_in[1];
    const float* noise   = (const float*)d_in[2];
    const float* W_X     = (const float*)d_in[3];
    const float* b_X     = (const float*)d_in[4];
    const float* W_emb   = (const float*)d_in[5];
    const float* b_emb   = (const float*)d_in[6];
    const float* Wf1     = (const float*)d_in[7];
    const float* bf1     = (const float*)d_in[8];
    const float* Wf2     = (const float*)d_in[9];
    const float* bf2     = (const float*)d_in[10];
    const float* W_out   = (const float*)d_in[11];
    const float* b_out   = (const float*)d_in[12];
    const float* W_noise = (const float*)d_in[13];
    const float* b_noise = (const float*)d_in[14];
    const float* Wg1     = (const float*)d_in[15];
    const float* bg1     = (const float*)d_in[16];
    const float* Wg2     = (const float*)d_in[17];
    const float* bg2     = (const float*)d_in[18];
    const float* W_init  = (const float*)d_in[19];
    const float* b_init  = (const float*)d_in[20];
    const float* W_dec   = (const float*)d_in[21];
    const float* b_dec   = (const float*)d_in[22];
    const float* W_cls   = (const float*)d_in[23];
    const float* b_cls   = (const float*)d_in[24];
    const int*   mask    = (const int*)  d_in[25];
    float* out = (float*)d_out;

    float *pP, *pZ, *pPred, *pWyf, *pW2o, *pB2o, *pM, *pM2,
          *pTT, *pG1, *pGT, *pCvec, *pTmpv;
    cudaGetSymbolAddress((void**)&pP,    g_P);
    cudaGetSymbolAddress((void**)&pZ,    g_Z);
    cudaGetSymbolAddress((void**)&pPred, g_predtmp);
    cudaGetSymbolAddress((void**)&pWyf,  g_Wyf);
    cudaGetSymbolAddress((void**)&pW2o,  g_W2o);
    cudaGetSymbolAddress((void**)&pB2o,  g_b2o);
    cudaGetSymbolAddress((void**)&pM,    g_M);
    cudaGetSymbolAddress((void**)&pM2,   g_M2);
    cudaGetSymbolAddress((void**)&pTT,   g_tt);
    cudaGetSymbolAddress((void**)&pG1,   g_G1);
    cudaGetSymbolAddress((void**)&pGT,   g_gt);
    cudaGetSymbolAddress((void**)&pCvec, g_cvec);
    cudaGetSymbolAddress((void**)&pTmpv, g_tmpvec);

    // allow >48KB dynamic smem for the persistent scan kernel
    cudaFuncSetAttribute(scan_kernel,
                         cudaFuncAttributeMaxDynamicSharedMemorySize, SMEM_BYTES);

    // 1. prep: tt, dts, sqrt(dts), last_idx, barrier reset
    prep_kernel<<<(TSTEPS * HD + 255) / 256, 256>>>(times, W_noise, b_noise, mask);

    // 2. diffusion path: G1 = lipswish(tt@Wg1+bg1); gt = G1@Wg2+bg2
    gemm_generic<<<dim3(16, 7), 256>>>(pTT, HD, Wg1, HD, bg1, 0, pG1, HD,
                                       TSTEPS, HD, HD, ACT_LIP);
    gemm_generic<<<dim3(16, 7), 256>>>(pG1, HD, Wg2, HD, bg2, 0, pGT, HD,
                                       TSTEPS, HD, HD, ACT_NONE);

    // 3. weight folds
    gemm_generic<<<dim3(16, 2), 256>>>(W_X, HD, W_emb + HD * HD, HD, nullptr, 0,
                                       pM2, HD, DIN, HD, HD, ACT_NONE);
    gemm_generic<<<dim3(16, 2), 256>>>(pM2, HD, Wf1, HD, nullptr, 0,
                                       pM, HD, DIN, HD, HD, ACT_NONE);
    gemm_generic<<<dim3(16, 1), 256>>>(b_X, HD, W_emb + HD * HD, HD, b_emb, 0,
                                       pTmpv, HD, 1, HD, HD, ACT_NONE);
    gemm_generic<<<dim3(16, 1), 256>>>(pTmpv, HD, Wf1, HD, bf1, 0,
                                       pCvec, HD, 1, HD, HD, ACT_NONE);
    gemm_generic<<<dim3(16, 16), 256>>>(W_emb, HD, Wf1, HD, nullptr, 0,
                                        pWyf, HD, HD, HD, HD, ACT_NONE);
    //    W2o = Wf2 @ W_out ;  b2o = bf2 @ W_out + b_out
    gemm_generic<<<dim3(16, 16), 256>>>(Wf2, HD, W_out, HD, nullptr, 0,
                                        pW2o, HD, HD, HD, HD, ACT_NONE);
    gemm_generic<<<dim3(16, 1), 256>>>(bf2, HD, W_out, HD, b_out, 0,
                                       pB2o, HD, 1, HD, HD, ACT_NONE);

    // 4. y0 = a[:,0,:] @ W_init + b_init
    gemm_generic<<<dim3(16, 8), 256>>>(coeffs, TSTEPS * 256, W_init, HD, b_init, 0,
                                       pZ, HD, BSZ, HD, DIN, ACT_NONE);

    // 5. P[t] = a[:,t,:] @ M + cvec  (fully parallel over t)
    kernel_P<<<dim3(8, 8, TSTEPS), 256>>>(coeffs);

    // 6. entire 199-step scan in ONE persistent kernel (128 co-resident CTAs,
    //    persistent smem weights, group-local barriers)
    scan_kernel<<<RG * GROUP_CTAS, 256, SMEM_BYTES>>>(noise);

    // 7. decode + reorder
    gemm_generic<<<dim3(2, 1600), 256>>>(pZ, HD, W_dec, DOUT, b_dec, 0,
                                         pPred, DOUT, TTOT * BSZ, DOUT, HD, ACT_NONE);
    reorder_kernel<<<(TTOT * BSZ * DOUT + 255) / 256, 256>>>(out);

    // 8. classifier logits
    cls_kernel<<<BSZ, 320>>>(W_cls, b_cls, out + (size_t)TTOT * BSZ * DOUT);
}

// round 12
// speedup vs baseline: 3.0273x; 1.1980x over previous
#include <cuda_runtime.h>
#include <math.h>

// Problem constants
#define TSTEPS 199
#define TTOT   200
#define BSZ    256
#define HD     512
#define BH     (BSZ*HD)        // 131072
#define DIN    64
#define DOUT   64
#define NCLS   10
#define LIPC   0.909f

#define ACT_NONE 0
#define ACT_LIP  1

#define RG         8    // row groups (32 rows each)
#define GROUP_CTAS 16   // col CTAs per group (32 cols each)

#define APAD  516                      // A row stride (floats), mult of 4 for float4 STS
#define WPAD  514                      // weight col stride; WPAD/2=257 odd -> conflict-free LDS.64
#define ASZ   (32*APAD)                // 16512 floats
#define WSZ   (32*WPAD)                // 16448 floats
#define SMEM_BYTES ((2*WSZ + ASZ)*4)   // Wy + Wo + A = 197632 bytes

typedef unsigned long long u64;

// packed fp32x2 FMA (FFMA2): acc.(lo,hi) += a.(lo,hi)*b.(lo,hi)
#define FMA2(acc, a, b) \
    asm("fma.rn.f32x2 %0, %1, %2, %0;" : "+l"(acc) : "l"(a), "l"(b))

__device__ __forceinline__ float hsum2(u64 q) {
    float lo, hi;
    asm("mov.b64 {%0,%1}, %2;" : "=f"(lo), "=f"(hi) : "l"(q));
    return lo + hi;
}

// ---------------- scratch (static device globals; no allocation) ----------------
__device__ __align__(256) float g_P[TSTEPS*BH];            // folded x-path bias  ~104MB
__device__ __align__(256) float g_Z[TTOT*BH];              // trajectory          ~105MB
__device__ __align__(256) float g_predtmp[TTOT*BSZ*DOUT];  // decode (t,b) order
__device__ __align__(256) float g_h[BH];
__device__ __align__(256) float g_Wyf[HD*HD];              // W_emb_y @ Wf1
__device__ __align__(256) float g_W2o[HD*HD];              // Wf2 @ W_out (fold)
__device__ __align__(256) float g_b2o[HD];                 // bf2 @ W_out + b_out
__device__ __align__(256) float g_M[DIN*HD];               // W_X @ W_emb_x @ Wf1
__device__ __align__(256) float g_M2[DIN*HD];
__device__ __align__(256) float g_tt[TSTEPS*HD];
__device__ __align__(256) float g_G1[TSTEPS*HD];
__device__ __align__(256) float g_gt[TSTEPS*HD];
__device__ __align__(256) float g_cvec[HD];
__device__ __align__(256) float g_tmpvec[HD];
__device__ float g_dts[TSTEPS];
__device__ float g_sqdts[TSTEPS];
__device__ int   g_lastidx[BSZ];
__device__ unsigned g_barctr[RG];

__device__ __forceinline__ float lipswish(float x) {
    return LIPC * x / (1.0f + __expf(-x));
}

// ---------------- prep: tt, dts, sqrt(dts), last_idx, barrier counters -------
__global__ void prep_kernel(const float* __restrict__ times,
                            const float* __restrict__ W_noise,
                            const float* __restrict__ b_noise,
                            const int*   __restrict__ mask)
{
    int idx = blockIdx.x * blockDim.x + threadIdx.x;
    if (idx < TSTEPS * HD) {
        int t = idx >> 9, h = idx & (HD - 1);
        g_tt[idx] = times[t] * W_noise[h] + b_noise[h];
    }
    if (idx < TSTEPS) {
        float d = times[idx + 1] - times[idx];
        g_dts[idx] = d;
        g_sqdts[idx] = sqrtf(d);
    }
    if (idx < BSZ) {
        int s = 0;
        for (int t = 0; t < TTOT; t++) s += mask[idx * TTOT + t];
        int li = s - 1;
        if (li < 0) li = 0;
        if (li > TTOT - 1) li = TTOT - 1;
        g_lastidx[idx] = li;
    }
    if (idx < RG) g_barctr[idx] = 0u;   // reset group barriers every replay
}

// ---------------- generic fp32 GEMM: C = act(A@B + bias) ----------------
__global__ void gemm_generic(const float* __restrict__ A, int lda,
                             const float* __restrict__ B, int ldb,
                             const float* __restrict__ bias, int bias_stride,
                             float* __restrict__ C, int ldc,
                             int M, int N, int K, int act)
{
    __shared__ float As[32][33];
    __shared__ float Bs[32][33];
    int tid = threadIdx.x;
    int tx = tid & 15, ty = tid >> 4;
    int rowBase = blockIdx.y * 32;
    int colBase = blockIdx.x * 32;

    float acc00 = 0.f, acc01 = 0.f, acc10 = 0.f, acc11 = 0.f;

    for (int k0 = 0; k0 < K; k0 += 32) {
        #pragma unroll
        for (int i = 0; i < 4; i++) {
            int idx = tid + i * 256;
            int r = idx >> 5, c = idx & 31;
            int ar = rowBase + r, ac = k0 + c;
            As[r][c] = (ar < M && ac < K) ? A[(size_t)ar * lda + ac] : 0.f;
            int br = k0 + r, bc = colBase + c;
            Bs[r][c] = (br < K && bc < N) ? B[(size_t)br * ldb + bc] : 0.f;
        }
        __syncthreads();
        #pragma unroll
        for (int kk = 0; kk < 32; kk++) {
            float a0 = As[ty][kk], a1 = As[ty + 16][kk];
            float b0 = Bs[kk][tx], b1 = Bs[kk][tx + 16];
            acc00 = fmaf(a0, b0, acc00);
            acc01 = fmaf(a0, b1, acc01);
            acc10 = fmaf(a1, b0, acc10);
            acc11 = fmaf(a1, b1, acc11);
        }
        __syncthreads();
    }

    int r0 = rowBase + ty, r1 = r0 + 16;
    int c0 = colBase + tx, c1 = c0 + 16;

    #pragma unroll
    for (int i = 0; i < 4; i++) {
        int r = (i & 2) ? r1 : r0;
        int c = (i & 1) ? c1 : c0;
        float v = (i == 0) ? acc00 : (i == 1) ? acc01 : (i == 2) ? acc10 : acc11;
        if (r < M && c < N) {
            if (bias) v += bias[(size_t)r * bias_stride + c];
            if (act == ACT_LIP) v = lipswish(v);
            C[(size_t)r * ldc + c] = v;
        }
    }
}

// ---------------- P precompute: P[t][b][n] = a[b,t,:] @ g_M + cvec[n] --------
__global__ void kernel_P(const float* __restrict__ coeffs)
{
    __shared__ float As[32][65];  // [b][d]
    __shared__ float Bs[64][65];  // [d][n]
    int t  = blockIdx.z;
    int b0 = blockIdx.y * 32;
    int n0 = blockIdx.x * 64;
    int tid = threadIdx.x;

    #pragma unroll
    for (int i = 0; i < 8; i++) {
        int idx = tid + i * 256;
        int r = idx >> 6, c = idx & 63;
        As[r][c] = coeffs[((size_t)(b0 + r) * TSTEPS + t) * 256 + c]; // a-part
    }
    #pragma unroll
    for (int i = 0; i < 16; i++) {
        int idx = tid + i * 256;
        int r = idx >> 6, c = idx & 63;
        Bs[r][c] = g_M[r * HD + n0 + c];
    }
    __syncthreads();

    int tx = tid & 15, ty = tid >> 4;
    float acc[2][4] = {};
    #pragma unroll
    for (int k = 0; k < 64; k++) {
        float a0 = As[ty][k], a1 = As[ty + 16][k];
        #pragma unroll
        for (int j = 0; j < 4; j++) {
            float b = Bs[k][tx * 4 + j];
            acc[0][j] = fmaf(a0, b, acc[0][j]);
            acc[1][j] = fmaf(a1, b, acc[1][j]);
        }
    }
    #pragma unroll
    for (int ri = 0; ri < 2; ri++) {
        int r = b0 + ty + ri * 16;
        #pragma unroll
        for (int j = 0; j < 4; j++) {
            int c = n0 + tx * 4 + j;
            g_P[(size_t)t * BH + (size_t)r * HD + c] = acc[ri][j] + g_cvec[c];
        }
    }
}

// ---------------- group-local spin barrier (16 CTAs, all co-resident) --------
__device__ __forceinline__ void group_barrier(int g, unsigned target)
{
    __syncthreads();
    if (threadIdx.x == 0) {
        __threadfence();
        atomicAdd(&g_barctr[g], 1u);
        while (*(volatile unsigned*)&g_barctr[g] < target) __nanosleep(20);
        __threadfence();
    }
    __syncthreads();
}

// ---------------- persistent scan kernel -------------------------------------
// 128 CTAs = 8 row-groups (32 batch rows) x 16 col-CTAs (32 cols).
// Weight slices transposed col-major in smem (persistent). A tile row-major.
// k-loop uses packed fp32x2 FMA (FFMA2) accumulating (even-k, odd-k) partials.
__global__ void __launch_bounds__(256, 1)
scan_kernel(const float* __restrict__ noise)
{
    extern __shared__ float smem[];
    float* sWy = smem;                 // [32 cols][WPAD] col-major Wyf slice
    float* sWo = smem + WSZ;           // [32 cols][WPAD] col-major W2o slice
    float* sA  = smem + 2 * WSZ;       // [32 rows][APAD] row-major A tile

    const int g   = blockIdx.x >> 4;
    const int c0  = (blockIdx.x & 15) << 5;
    const int r0  = g << 5;
    const int tid = threadIdx.x;

    const int tx = tid & 15, ty = tid >> 4;
    const int ra = r0 + ty, rb = ra + 16;
    const int ca = c0 + tx, cb = ca + 16;
    const int lya = ty * APAD, lyb = (ty + 16) * APAD;
    const int lca = tx * WPAD, lcb = (tx + 16) * WPAD;

    // loader mapping for weight transpose: k = wk + 8*it, c = lane32
    const int lrow = tid & 31;
    const int wk   = tid >> 5;                // 0..7

    // ---- load + transpose persistent weight slices (once) ----
    #pragma unroll 4
    for (int it = 0; it < 64; it++) {
        int k = wk + (it << 3);
        sWy[lrow * WPAD + k] = g_Wyf[(size_t)k * HD + c0 + lrow];
        sWo[lrow * WPAD + k] = g_W2o[(size_t)k * HD + c0 + lrow];
    }

    const float b2a = g_b2o[ca];
    const float b2b = g_b2o[cb];

    unsigned target = GROUP_CTAS;

    for (int t = 0; t < TSTEPS; t++) {
        const float* Zt = g_Z + (size_t)t * BH;
        float*       Zn = g_Z + (size_t)(t + 1) * BH;

        // prefetch P[t] epilogue operands
        const float* Pt = g_P + (size_t)t * BH;
        float p00 = Pt[(size_t)ra * HD + ca];
        float p01 = Pt[(size_t)ra * HD + cb];
        float p10 = Pt[(size_t)rb * HD + ca];
        float p11 = Pt[(size_t)rb * HD + cb];

        // ---- fill A tile (row-major, straight float4 copy) ----
        {
            const float* src = Zt + (size_t)r0 * HD;
            #pragma unroll 4
            for (int it = 0; it < 16; it++) {
                int f4 = tid + (it << 8);
                int row = f4 >> 7, c4 = (f4 & 127) << 2;
                *(float4*)(sA + row * APAD + c4) =
                    *(const float4*)(src + (size_t)row * HD + c4);
            }
        }
        __syncthreads();

        // ---- GEMM1: h = lipswish(Zt_tile @ Wyf + P[t]) ----
        {
            u64 q00 = 0ull, q01 = 0ull, q10 = 0ull, q11 = 0ull;
            #pragma unroll 8
            for (int kp = 0; kp < 256; kp++) {
                u64 a0 = *(const u64*)(sA  + lya + (kp << 1));
                u64 a1 = *(const u64*)(sA  + lyb + (kp << 1));
                u64 b0 = *(const u64*)(sWy + lca + (kp << 1));
                u64 b1 = *(const u64*)(sWy + lcb + (kp << 1));
                FMA2(q00, a0, b0);
                FMA2(q01, a0, b1);
                FMA2(q10, a1, b0);
                FMA2(q11, a1, b1);
            }
            g_h[(size_t)ra * HD + ca] = lipswish(hsum2(q00) + p00);
            g_h[(size_t)ra * HD + cb] = lipswish(hsum2(q01) + p01);
            g_h[(size_t)rb * HD + ca] = lipswish(hsum2(q10) + p10);
            g_h[(size_t)rb * HD + cb] = lipswish(hsum2(q11) + p11);
        }
        group_barrier(g, target); target += GROUP_CTAS;

        // prefetch GEMM2 epilogue operands
        const float dt = g_dts[t], sq = g_sqdts[t];
        float ga = g_gt[t * HD + ca] * sq;
        float gb = g_gt[t * HD + cb] * sq;
        const float* Nt = noise + (size_t)t * BH;
        float n00 = Nt[(size_t)ra * HD + ca];
        float n01 = Nt[(size_t)ra * HD + cb];
        float n10 = Nt[(size_t)rb * HD + ca];
        float n11 = Nt[(size_t)rb * HD + cb];
        float z00 = Zt[(size_t)ra * HD + ca];
        float z01 = Zt[(size_t)ra * HD + cb];
        float z10 = Zt[(size_t)rb * HD + ca];
        float z11 = Zt[(size_t)rb * HD + cb];

        // ---- fill A tile = h (row-major) ----
        {
            const float* src = g_h + (size_t)r0 * HD;
            #pragma unroll 4
            for (int it = 0; it < 16; it++) {
                int f4 = tid + (it << 8);
                int row = f4 >> 7, c4 = (f4 & 127) << 2;
                *(float4*)(sA + row * APAD + c4) =
                    *(const float4*)(src + (size_t)row * HD + c4);
            }
        }
        __syncthreads();

        // ---- GEMM2: y_{t+1} = y + (h @ W2o + b2o)*dt + gt*noise*sq ----
        {
            u64 q00 = 0ull, q01 = 0ull, q10 = 0ull, q11 = 0ull;
            #pragma unroll 8
            for (int kp = 0; kp < 256; kp++) {
                u64 a0 = *(const u64*)(sA  + lya + (kp << 1));
                u64 a1 = *(const u64*)(sA  + lyb + (kp << 1));
                u64 b0 = *(const u64*)(sWo + lca + (kp << 1));
                u64 b1 = *(const u64*)(sWo + lcb + (kp << 1));
                FMA2(q00, a0, b0);
                FMA2(q01, a0, b1);
                FMA2(q10, a1, b0);
                FMA2(q11, a1, b1);
            }
            Zn[(size_t)ra * HD + ca] = z00 + (hsum2(q00) + b2a) * dt + ga * n00;
            Zn[(size_t)ra * HD + cb] = z01 + (hsum2(q01) + b2b) * dt + gb * n01;
            Zn[(size_t)rb * HD + ca] = z10 + (hsum2(q10) + b2a) * dt + ga * n10;
            Zn[(size_t)rb * HD + cb] = z11 + (hsum2(q11) + b2b) * dt + gb * n11;
        }
        group_barrier(g, target); target += GROUP_CTAS;
    }
}

// ---------------- reorder decode output (t,b,d) -> (b,t,d) ----------------
__global__ void reorder_kernel(float* __restrict__ out)
{
    int idx = blockIdx.x * blockDim.x + threadIdx.x;
    if (idx < TTOT * BSZ * DOUT) {
        int d = idx & 63;
        int r = idx >> 6;         // r = t*BSZ + b
        int tpos = r >> 8;
        int b = r & 255;
        out[((size_t)b * TTOT + tpos) * DOUT + d] = g_predtmp[idx];
    }
}

// ---------------- classifier: logits = z[last_idx] @ W_cls + b_cls ----------
__global__ void cls_kernel(const float* __restrict__ W_cls,
                           const float* __restrict__ b_cls,
                           float* __restrict__ logits)
{
    int b = blockIdx.x;
    int w = threadIdx.x >> 5, lane = threadIdx.x & 31;
    if (w >= NCLS) return;
    int li = g_lastidx[b];
    const float* z = g_Z + ((size_t)li * BSZ + b) * HD;
    float s = 0.f;
    for (int h = lane; h < HD; h += 32)
        s += z[h] * W_cls[h * NCLS + w];
    #pragma unroll
    for (int o = 16; o; o >>= 1) s += __shfl_down_sync(0xffffffffu, s, o);
    if (lane == 0) logits[b * NCLS + w] = s + b_cls[w];
}

// ---------------- launch ----------------
extern "C" void kernel_launch(void* const* d_in, const int* in_sizes, int n_in,
                              void* d_out, int out_size)
{
    const float* coeffs  = (const float*)d_in[0];
    const float* times   = (const float*)d_in[1];
    const float* noise   = (const float*)d_in[2];
    const float* W_X     = (const float*)d_in[3];
    const float* b_X     = (const float*)d_in[4];
    const float* W_emb   = (const float*)d_in[5];
    const float* b_emb   = (const float*)d_in[6];
    const float* Wf1     = (const float*)d_in[7];
    const float* bf1     = (const float*)d_in[8];
    const float* Wf2     = (const float*)d_in[9];
    const float* bf2     = (const float*)d_in[10];
    const float* W_out   = (const float*)d_in[11];
    const float* b_out   = (const float*)d_in[12];
    const float* W_noise = (const float*)d_in[13];
    const float* b_noise = (const float*)d_in[14];
    const float* Wg1     = (const float*)d_in[15];
    const float* bg1     = (const float*)d_in[16];
    const float* Wg2     = (const float*)d_in[17];
    const float* bg2     = (const float*)d_in[18];
    const float* W_init  = (const float*)d_in[19];
    const float* b_init  = (const float*)d_in[20];
    const float* W_dec   = (const float*)d_in[21];
    const float* b_dec   = (const float*)d_in[22];
    const float* W_cls   = (const float*)d_in[23];
    const float* b_cls   = (const float*)d_in[24];
    const int*   mask    = (const int*)  d_in[25];
    float* out = (float*)d_out;

    float *pP, *pZ, *pPred, *pWyf, *pW2o, *pB2o, *pM, *pM2,
          *pTT, *pG1, *pGT, *pCvec, *pTmpv;
    cudaGetSymbolAddress((void**)&pP,    g_P);
    cudaGetSymbolAddress((void**)&pZ,    g_Z);
    cudaGetSymbolAddress((void**)&pPred, g_predtmp);
    cudaGetSymbolAddress((void**)&pWyf,  g_Wyf);
    cudaGetSymbolAddress((void**)&pW2o,  g_W2o);
    cudaGetSymbolAddress((void**)&pB2o,  g_b2o);
    cudaGetSymbolAddress((void**)&pM,    g_M);
    cudaGetSymbolAddress((void**)&pM2,   g_M2);
    cudaGetSymbolAddress((void**)&pTT,   g_tt);
    cudaGetSymbolAddress((void**)&pG1,   g_G1);
    cudaGetSymbolAddress((void**)&pGT,   g_gt);
    cudaGetSymbolAddress((void**)&pCvec, g_cvec);
    cudaGetSymbolAddress((void**)&pTmpv, g_tmpvec);

    // allow >48KB dynamic smem for the persistent scan kernel
    cudaFuncSetAttribute(scan_kernel,
                         cudaFuncAttributeMaxDynamicSharedMemorySize, SMEM_BYTES);

    // 1. prep: tt, dts, sqrt(dts), last_idx, barrier reset
    prep_kernel<<<(TSTEPS * HD + 255) / 256, 256>>>(times, W_noise, b_noise, mask);

    // 2. diffusion path: G1 = lipswish(tt@Wg1+bg1); gt = G1@Wg2+bg2
    gemm_generic<<<dim3(16, 7), 256>>>(pTT, HD, Wg1, HD, bg1, 0, pG1, HD,
                                       TSTEPS, HD, HD, ACT_LIP);
    gemm_generic<<<dim3(16, 7), 256>>>(pG1, HD, Wg2, HD, bg2, 0, pGT, HD,
                                       TSTEPS, HD, HD, ACT_NONE);

    // 3. weight folds
    gemm_generic<<<dim3(16, 2), 256>>>(W_X, HD, W_emb + HD * HD, HD, nullptr, 0,
                                       pM2, HD, DIN, HD, HD, ACT_NONE);
    gemm_generic<<<dim3(16, 2), 256>>>(pM2, HD, Wf1, HD, nullptr, 0,
                                       pM, HD, DIN, HD, HD, ACT_NONE);
    gemm_generic<<<dim3(16, 1), 256>>>(b_X, HD, W_emb + HD * HD, HD, b_emb, 0,
                                       pTmpv, HD, 1, HD, HD, ACT_NONE);
    gemm_generic<<<dim3(16, 1), 256>>>(pTmpv, HD, Wf1, HD, bf1, 0,
                                       pCvec, HD, 1, HD, HD, ACT_NONE);
    gemm_generic<<<dim3(16, 16), 256>>>(W_emb, HD, Wf1, HD, nullptr, 0,
                                        pWyf, HD, HD, HD, HD, ACT_NONE);
    //    W2o = Wf2 @ W_out ;  b2o = bf2 @ W_out + b_out
    gemm_generic<<<dim3(16, 16), 256>>>(Wf2, HD, W_out, HD, nullptr, 0,
                                        pW2o, HD, HD, HD, HD, ACT_NONE);
    gemm_generic<<<dim3(16, 1), 256>>>(bf2, HD, W_out, HD, b_out, 0,
                                       pB2o, HD, 1, HD, HD, ACT_NONE);

    // 4. y0 = a[:,0,:] @ W_init + b_init
    gemm_generic<<<dim3(16, 8), 256>>>(coeffs, TSTEPS * 256, W_init, HD, b_init, 0,
                                       pZ, HD, BSZ, HD, DIN, ACT_NONE);

    // 5. P[t] = a[:,t,:] @ M + cvec  (fully parallel over t)
    kernel_P<<<dim3(8, 8, TSTEPS), 256>>>(coeffs);

    // 6. entire 199-step scan in ONE persistent kernel (128 co-resident CTAs,
    //    persistent transposed smem weights, FFMA2 k-pair inner loops)
    scan_kernel<<<RG * GROUP_CTAS, 256, SMEM_BYTES>>>(noise);

    // 7. decode + reorder
    gemm_generic<<<dim3(2, 1600), 256>>>(pZ, HD, W_dec, DOUT, b_dec, 0,
                                         pPred, DOUT, TTOT * BSZ, DOUT, HD, ACT_NONE);
    reorder_kernel<<<(TTOT * BSZ * DOUT + 255) / 256, 256>>>(out);

    // 8. classifier logits
    cls_kernel<<<BSZ, 320>>>(W_cls, b_cls, out + (size_t)TTOT * BSZ * DOUT);
}

// round 14
// speedup vs baseline: 3.1297x; 1.0338x over previous
#include <cuda_runtime.h>
#include <math.h>

// Problem constants
#define TSTEPS 199
#define TTOT   200
#define BSZ    256
#define HD     512
#define BH     (BSZ*HD)        // 131072
#define DIN    64
#define DOUT   64
#define NCLS   10
#define LIPC   0.909f

#define ACT_NONE   0
#define ACT_LIP    1
#define ACT_DECODE 2

#define RG         8    // row groups (32 rows each)
#define GROUP_CTAS 16   // col CTAs per group (32 cols each)

#define APAD  516                      // A row stride (floats)
#define WPAD  516                      // weight col stride
#define ASZ   (32*APAD)
#define WSZ   (32*WPAD)
#define SMEM_BYTES ((2*WSZ + ASZ)*4)   // Wy + Wo + A = 198144 bytes

typedef unsigned long long u64;

// packed fp32x2 FMA (FFMA2): acc.(lo,hi) += a.(lo,hi)*b.(lo,hi)
#define FMA2(acc, a, b) \
    asm("fma.rn.f32x2 %0, %1, %2, %0;" : "+l"(acc) : "l"(a), "l"(b))

__device__ __forceinline__ float hsum2(u64 q) {
    float lo, hi;
    asm("mov.b64 {%0,%1}, %2;" : "=f"(lo), "=f"(hi) : "l"(q));
    return lo + hi;
}

// ---------------- scratch (static device globals; no allocation) ----------------
__device__ __align__(256) float g_P[TSTEPS*BH];            // folded x-path bias  ~104MB
__device__ __align__(256) float g_Z[TTOT*BH];              // trajectory          ~105MB
__device__ __align__(256) float g_h[BH];
__device__ __align__(256) float g_Wyf[HD*HD];              // W_emb_y @ Wf1
__device__ __align__(256) float g_W2o[HD*HD];              // Wf2 @ W_out
__device__ __align__(256) float g_E[HD*HD];                // W_emb_x @ Wf1
__device__ __align__(256) float g_b2o[HD];                 // bf2 @ W_out + b_out
__device__ __align__(256) float g_bvec1[HD];               // b_emb @ Wf1 + bf1
__device__ __align__(256) float g_M[DIN*HD];               // W_X @ E
__device__ __align__(256) float g_tt[TSTEPS*HD];
__device__ __align__(256) float g_G1[TSTEPS*HD];
__device__ __align__(256) float g_gt[TSTEPS*HD];
__device__ __align__(256) float g_cvec[HD];
__device__ float g_dts[TSTEPS];
__device__ float g_sqdts[TSTEPS];
__device__ int   g_lastidx[BSZ];
__device__ unsigned g_barctr[RG];

__device__ __forceinline__ float lipswish(float x) {
    return LIPC * x / (1.0f + __expf(-x));
}

// ---------------- prep: tt, dts, sqrt(dts), last_idx, barrier counters -------
__global__ void prep_kernel(const float* __restrict__ times,
                            const float* __restrict__ W_noise,
                            const float* __restrict__ b_noise,
                            const int*   __restrict__ mask)
{
    int idx = blockIdx.x * blockDim.x + threadIdx.x;
    if (idx < TSTEPS * HD) {
        int t = idx >> 9, h = idx & (HD - 1);
        g_tt[idx] = times[t] * W_noise[h] + b_noise[h];
    }
    if (idx < TSTEPS) {
        float d = times[idx + 1] - times[idx];
        g_dts[idx] = d;
        g_sqdts[idx] = sqrtf(d);
    }
    if (idx < BSZ) {
        int s = 0;
        for (int t = 0; t < TTOT; t++) s += mask[idx * TTOT + t];
        int li = s - 1;
        if (li < 0) li = 0;
        if (li > TTOT - 1) li = TTOT - 1;
        g_lastidx[idx] = li;
    }
    if (idx < RG) g_barctr[idx] = 0u;   // reset group barriers every replay
}

// ---------------- 32x32 GEMM tile device function ----------------------------
// C_tile(tileY, tileX) = act(A@B + bias). bias row-vector (stride 0) or matrix.
__device__ __forceinline__
void gemm_tile(const float* __restrict__ A, int lda,
               const float* __restrict__ B, int ldb,
               const float* __restrict__ bias, int bias_stride,
               float* __restrict__ C, int ldc,
               int M, int N, int K, int act, int tileX, int tileY,
               float As[32][33], float Bs[32][33])
{
    int tid = threadIdx.x;
    int tx = tid & 15, ty = tid >> 4;
    int rowBase = tileY * 32;
    int colBase = tileX * 32;

    float acc00 = 0.f, acc01 = 0.f, acc10 = 0.f, acc11 = 0.f;

    for (int k0 = 0; k0 < K; k0 += 32) {
        #pragma unroll
        for (int i = 0; i < 4; i++) {
            int idx = tid + i * 256;
            int r = idx >> 5, c = idx & 31;
            int ar = rowBase + r, ac = k0 + c;
            As[r][c] = (ar < M && ac < K) ? A[(size_t)ar * lda + ac] : 0.f;
            int br = k0 + r, bc = colBase + c;
            Bs[r][c] = (br < K && bc < N) ? B[(size_t)br * ldb + bc] : 0.f;
        }
        __syncthreads();
        #pragma unroll
        for (int kk = 0; kk < 32; kk++) {
            float a0 = As[ty][kk], a1 = As[ty + 16][kk];
            float b0 = Bs[kk][tx], b1 = Bs[kk][tx + 16];
            acc00 = fmaf(a0, b0, acc00);
            acc01 = fmaf(a0, b1, acc01);
            acc10 = fmaf(a1, b0, acc10);
            acc11 = fmaf(a1, b1, acc11);
        }
        __syncthreads();
    }

    int r0 = rowBase + ty, r1 = r0 + 16;
    int c0 = colBase + tx, c1 = c0 + 16;

    #pragma unroll
    for (int i = 0; i < 4; i++) {
        int r = (i & 2) ? r1 : r0;
        int c = (i & 1) ? c1 : c0;
        float v = (i == 0) ? acc00 : (i == 1) ? acc01 : (i == 2) ? acc10 : acc11;
        if (r < M && c < N) {
            if (bias) v += bias[(size_t)r * bias_stride + c];
            if (act == ACT_LIP) v = lipswish(v);
            if (act == ACT_DECODE) {
                // r = t*BSZ + b  ->  out[(b*TTOT + t)*DOUT + c]
                C[((size_t)(r & 255) * TTOT + (r >> 8)) * DOUT + c] = v;
            } else {
                C[(size_t)r * ldc + c] = v;
            }
        }
    }
}

// generic standalone GEMM (used for decode)
__global__ void gemm_generic(const float* __restrict__ A, int lda,
                             const float* __restrict__ B, int ldb,
                             const float* __restrict__ bias, int bias_stride,
                             float* __restrict__ C, int ldc,
                             int M, int N, int K, int act)
{
    __shared__ float As[32][33];
    __shared__ float Bs[32][33];
    gemm_tile(A, lda, B, ldb, bias, bias_stride, C, ldc, M, N, K, act,
              blockIdx.x, blockIdx.y, As, Bs);
}

// ---------------- stage A: all independent prolog GEMMs in one launch --------
// blocks: [0,256) Wyf | [256,512) E | [512,768) W2o | [768,880) G1
//         [880,1008) y0 | [1008,1024) b2o | [1024,1040) bvec1
__global__ void stageA_kernel(const float* __restrict__ W_emb,
                              const float* __restrict__ Wf1,
                              const float* __restrict__ Wf2,
                              const float* __restrict__ W_out,
                              const float* __restrict__ b_out,
                              const float* __restrict__ Wg1,
                              const float* __restrict__ bg1,
                              const float* __restrict__ coeffs,
                              const float* __restrict__ W_init,
                              const float* __restrict__ b_init,
                              const float* __restrict__ bf2,
                              const float* __restrict__ b_emb,
                              const float* __restrict__ bf1)
{
    __shared__ float As[32][33];
    __shared__ float Bs[32][33];
    int b = blockIdx.x;
    if (b < 256) {
        gemm_tile(W_emb, HD, Wf1, HD, nullptr, 0, g_Wyf, HD,
                  HD, HD, HD, ACT_NONE, b & 15, b >> 4, As, Bs);
    } else if (b < 512) {
        int l = b - 256;
        gemm_tile(W_emb + (size_t)HD * HD, HD, Wf1, HD, nullptr, 0, g_E, HD,
                  HD, HD, HD, ACT_NONE, l & 15, l >> 4, As, Bs);
    } else if (b < 768) {
        int l = b - 512;
        gemm_tile(Wf2, HD, W_out, HD, nullptr, 0, g_W2o, HD,
                  HD, HD, HD, ACT_NONE, l & 15, l >> 4, As, Bs);
    } else if (b < 880) {
        int l = b - 768;
        gemm_tile(g_tt, HD, Wg1, HD, bg1, 0, g_G1, HD,
                  TSTEPS, HD, HD, ACT_LIP, l & 15, l >> 4, As, Bs);
    } else if (b < 1008) {
        int l = b - 880;
        gemm_tile(coeffs, TSTEPS * 256, W_init, HD, b_init, 0, g_Z, HD,
                  BSZ, HD, DIN, ACT_NONE, l & 15, l >> 4, As, Bs);
    } else if (b < 1024) {
        int l = b - 1008;
        gemm_tile(bf2, HD, W_out, HD, b_out, 0, g_b2o, HD,
                  1, HD, HD, ACT_NONE, l, 0, As, Bs);
    } else {
        int l = b - 1024;
        gemm_tile(b_emb, HD, Wf1, HD, bf1, 0, g_bvec1, HD,
                  1, HD, HD, ACT_NONE, l, 0, As, Bs);
    }
}

// ---------------- stage B: dependent prolog GEMMs ----------------------------
// blocks: [0,32) M = W_X@E | [32,48) cvec = b_X@E + bvec1 | [48,160) gt
__global__ void stageB_kernel(const float* __restrict__ W_X,
                              const float* __restrict__ b_X,
                              const float* __restrict__ Wg2,
                              const float* __restrict__ bg2)
{
    __shared__ float As[32][33];
    __shared__ float Bs[32][33];
    int b = blockIdx.x;
    if (b < 32) {
        gemm_tile(W_X, HD, g_E, HD, nullptr, 0, g_M, HD,
                  DIN, HD, HD, ACT_NONE, b & 15, b >> 4, As, Bs);
    } else if (b < 48) {
        int l = b - 32;
        gemm_tile(b_X, HD, g_E, HD, g_bvec1, 0, g_cvec, HD,
                  1, HD, HD, ACT_NONE, l, 0, As, Bs);
    } else {
        int l = b - 48;
        gemm_tile(g_G1, HD, Wg2, HD, bg2, 0, g_gt, HD,
                  TSTEPS, HD, HD, ACT_NONE, l & 15, l >> 4, As, Bs);
    }
}

// ---------------- P precompute: P[t][b][n] = a[b,t,:] @ g_M + cvec[n] --------
__global__ void kernel_P(const float* __restrict__ coeffs)
{
    __shared__ float As[32][65];  // [b][d]
    __shared__ float Bs[64][65];  // [d][n]
    int t  = blockIdx.z;
    int b0 = blockIdx.y * 32;
    int n0 = blockIdx.x * 64;
    int tid = threadIdx.x;

    #pragma unroll
    for (int i = 0; i < 8; i++) {
        int idx = tid + i * 256;
        int r = idx >> 6, c = idx & 63;
        As[r][c] = coeffs[((size_t)(b0 + r) * TSTEPS + t) * 256 + c]; // a-part
    }
    #pragma unroll
    for (int i = 0; i < 16; i++) {
        int idx = tid + i * 256;
        int r = idx >> 6, c = idx & 63;
        Bs[r][c] = g_M[r * HD + n0 + c];
    }
    __syncthreads();

    int tx = tid & 15, ty = tid >> 4;
    float acc[2][4] = {};
    #pragma unroll
    for (int k = 0; k < 64; k++) {
        float a0 = As[ty][k], a1 = As[ty + 16][k];
        #pragma unroll
        for (int j = 0; j < 4; j++) {
            float b = Bs[k][tx * 4 + j];
            acc[0][j] = fmaf(a0, b, acc[0][j]);
            acc[1][j] = fmaf(a1, b, acc[1][j]);
        }
    }
    #pragma unroll
    for (int ri = 0; ri < 2; ri++) {
        int r = b0 + ty + ri * 16;
        #pragma unroll
        for (int j = 0; j < 4; j++) {
            int c = n0 + tx * 4 + j;
            g_P[(size_t)t * BH + (size_t)r * HD + c] = acc[ri][j] + g_cvec[c];
        }
    }
}

// ---------------- group-local barrier: release-add + acquire-poll ------------
__device__ __forceinline__ void group_barrier(int g, unsigned target)
{
    __syncthreads();
    if (threadIdx.x == 0) {
        unsigned* ctr = &g_barctr[g];
        asm volatile("red.release.gpu.global.add.u32 [%0], 1;"
                     :: "l"(ctr) : "memory");
        unsigned v;
        do {
            asm volatile("ld.acquire.gpu.global.u32 %0, [%1];"
                         : "=r"(v) : "l"(ctr) : "memory");
        } while (v < target);
    }
    __syncthreads();
}

// ---------------- persistent scan kernel -------------------------------------
// 128 CTAs = 8 row-groups (32 batch rows) x 16 col-CTAs (32 cols).
// Weights transposed col-major in smem (persistent); A tile row-major.
// k-loop: LDS.128 (4-k chunks) + FFMA2 (even/odd-k paired accumulators).
__global__ void __launch_bounds__(256, 1)
scan_kernel(const float* __restrict__ noise)
{
    extern __shared__ float smem[];
    float* sWy = smem;                 // [32 cols][WPAD]
    float* sWo = smem + WSZ;           // [32 cols][WPAD]
    float* sA  = smem + 2 * WSZ;       // [32 rows][APAD]

    const int g   = blockIdx.x >> 4;
    const int c0  = (blockIdx.x & 15) << 5;
    const int r0  = g << 5;
    const int tid = threadIdx.x;

    const int tx = tid & 15, ty = tid >> 4;
    const int ra = r0 + ty, rb = ra + 16;
    const int ca = c0 + tx, cb = ca + 16;
    const int lya = ty * APAD, lyb = (ty + 16) * APAD;
    const int lca = tx * WPAD, lcb = (tx + 16) * WPAD;

    // loader mapping for weight transpose
    const int lrow = tid & 31;
    const int wk   = tid >> 5;

    // ---- load + transpose persistent weight slices (once) ----
    #pragma unroll 4
    for (int it = 0; it < 64; it++) {
        int k = wk + (it << 3);
        sWy[lrow * WPAD + k] = g_Wyf[(size_t)k * HD + c0 + lrow];
        sWo[lrow * WPAD + k] = g_W2o[(size_t)k * HD + c0 + lrow];
    }

    const float b2a = g_b2o[ca];
    const float b2b = g_b2o[cb];

    unsigned target = GROUP_CTAS;

    for (int t = 0; t < TSTEPS; t++) {
        const float* Zt = g_Z + (size_t)t * BH;
        float*       Zn = g_Z + (size_t)(t + 1) * BH;

        // prefetch P[t] epilogue operands
        const float* Pt = g_P + (size_t)t * BH;
        float p00 = Pt[(size_t)ra * HD + ca];
        float p01 = Pt[(size_t)ra * HD + cb];
        float p10 = Pt[(size_t)rb * HD + ca];
        float p11 = Pt[(size_t)rb * HD + cb];

        // ---- fill A tile (row-major float4 copy) ----
        {
            const float* src = Zt + (size_t)r0 * HD;
            #pragma unroll 4
            for (int it = 0; it < 16; it++) {
                int f4 = tid + (it << 8);
                int row = f4 >> 7, c4 = (f4 & 127) << 2;
                *(float4*)(sA + row * APAD + c4) =
                    *(const float4*)(src + (size_t)row * HD + c4);
            }
        }
        __syncthreads();

        // ---- GEMM1: h = lipswish(Zt_tile @ Wyf + P[t]) ----
        {
            u64 q00 = 0ull, q01 = 0ull, q10 = 0ull, q11 = 0ull;
            #pragma unroll 4
            for (int k4 = 0; k4 < 128; k4++) {
                ulonglong2 a0 = *(const ulonglong2*)(sA  + lya + (k4 << 2));
                ulonglong2 a1 = *(const ulonglong2*)(sA  + lyb + (k4 << 2));
                ulonglong2 b0 = *(const ulonglong2*)(sWy + lca + (k4 << 2));
                ulonglong2 b1 = *(const ulonglong2*)(sWy + lcb + (k4 << 2));
                FMA2(q00, a0.x, b0.x); FMA2(q00, a0.y, b0.y);
                FMA2(q01, a0.x, b1.x); FMA2(q01, a0.y, b1.y);
                FMA2(q10, a1.x, b0.x); FMA2(q10, a1.y, b0.y);
                FMA2(q11, a1.x, b1.x); FMA2(q11, a1.y, b1.y);
            }
            g_h[(size_t)ra * HD + ca] = lipswish(hsum2(q00) + p00);
            g_h[(size_t)ra * HD + cb] = lipswish(hsum2(q01) + p01);
            g_h[(size_t)rb * HD + ca] = lipswish(hsum2(q10) + p10);
            g_h[(size_t)rb * HD + cb] = lipswish(hsum2(q11) + p11);
        }
        group_barrier(g, target); target += GROUP_CTAS;

        // prefetch GEMM2 epilogue operands
        const float dt = g_dts[t], sq = g_sqdts[t];
        float ga = g_gt[t * HD + ca] * sq;
        float gb = g_gt[t * HD + cb] * sq;
        const float* Nt = noise + (size_t)t * BH;
        float n00 = Nt[(size_t)ra * HD + ca];
        float n01 = Nt[(size_t)ra * HD + cb];
        float n10 = Nt[(size_t)rb * HD + ca];
        float n11 = Nt[(size_t)rb * HD + cb];
        float z00 = Zt[(size_t)ra * HD + ca];
        float z01 = Zt[(size_t)ra * HD + cb];
        float z10 = Zt[(size_t)rb * HD + ca];
        float z11 = Zt[(size_t)rb * HD + cb];

        // ---- fill A tile = h ----
        {
            const float* src = g_h + (size_t)r0 * HD;
            #pragma unroll 4
            for (int it = 0; it < 16; it++) {
                int f4 = tid + (it << 8);
                int row = f4 >> 7, c4 = (f4 & 127) << 2;
                *(float4*)(sA + row * APAD + c4) =
                    *(const float4*)(src + (size_t)row * HD + c4);
            }
        }
        __syncthreads();

        // ---- GEMM2: y_{t+1} = y + (h @ W2o + b2o)*dt + gt*noise*sq ----
        {
            u64 q00 = 0ull, q01 = 0ull, q10 = 0ull, q11 = 0ull;
            #pragma unroll 4
            for (int k4 = 0; k4 < 128; k4++) {
                ulonglong2 a0 = *(const ulonglong2*)(sA  + lya + (k4 << 2));
                ulonglong2 a1 = *(const ulonglong2*)(sA  + lyb + (k4 << 2));
                ulonglong2 b0 = *(const ulonglong2*)(sWo + lca + (k4 << 2));
                ulonglong2 b1 = *(const ulonglong2*)(sWo + lcb + (k4 << 2));
                FMA2(q00, a0.x, b0.x); FMA2(q00, a0.y, b0.y);
                FMA2(q01, a0.x, b1.x); FMA2(q01, a0.y, b1.y);
                FMA2(q10, a1.x, b0.x); FMA2(q10, a1.y, b0.y);
                FMA2(q11, a1.x, b1.x); FMA2(q11, a1.y, b1.y);
            }
            Zn[(size_t)ra * HD + ca] = z00 + (hsum2(q00) + b2a) * dt + ga * n00;
            Zn[(size_t)ra * HD + cb] = z01 + (hsum2(q01) + b2b) * dt + gb * n01;
            Zn[(size_t)rb * HD + ca] = z10 + (hsum2(q10) + b2a) * dt + ga * n10;
            Zn[(size_t)rb * HD + cb] = z11 + (hsum2(q11) + b2b) * dt + gb * n11;
        }
        group_barrier(g, target); target += GROUP_CTAS;
    }
}

// ---------------- classifier: logits = z[last_idx] @ W_cls + b_cls ----------
__global__ void cls_kernel(const float* __restrict__ W_cls,
                           const float* __restrict__ b_cls,
                           float* __restrict__ logits)
{
    int b = blockIdx.x;
    int w = threadIdx.x >> 5, lane = threadIdx.x & 31;
    if (w >= NCLS) return;
    int li = g_lastidx[b];
    const float* z = g_Z + ((size_t)li * BSZ + b) * HD;
    float s = 0.f;
    for (int h = lane; h < HD; h += 32)
        s += z[h] * W_cls[h * NCLS + w];
    #pragma unroll
    for (int o = 16; o; o >>= 1) s += __shfl_down_sync(0xffffffffu, s, o);
    if (lane == 0) logits[b * NCLS + w] = s + b_cls[w];
}

// ---------------- launch ----------------
extern "C" void kernel_launch(void* const* d_in, const int* in_sizes, int n_in,
                              void* d_out, int out_size)
{
    const float* coeffs  = (const float*)d_in[0];
    const float* times   = (const float*)d_in[1];
    const float* noise   = (const float*)d_in[2];
    const float* W_X     = (const float*)d_in[3];
    const float* b_X     = (const float*)d_in[4];
    const float* W_emb   = (const float*)d_in[5];
    const float* b_emb   = (const float*)d_in[6];
    const float* Wf1     = (const float*)d_in[7];
    const float* bf1     = (const float*)d_in[8];
    const float* Wf2     = (const float*)d_in[9];
    const float* bf2     = (const float*)d_in[10];
    const float* W_out   = (const float*)d_in[11];
    const float* b_out   = (const float*)d_in[12];
    const float* W_noise = (const float*)d_in[13];
    const float* b_noise = (const float*)d_in[14];
    const float* Wg1     = (const float*)d_in[15];
    const float* bg1     = (const float*)d_in[16];
    const float* Wg2     = (const float*)d_in[17];
    const float* bg2     = (const float*)d_in[18];
    const float* W_init  = (const float*)d_in[19];
    const float* b_init  = (const float*)d_in[20];
    const float* W_dec   = (const float*)d_in[21];
    const float* b_dec   = (const float*)d_in[22];
    const float* W_cls   = (const float*)d_in[23];
    const float* b_cls   = (const float*)d_in[24];
    const int*   mask    = (const int*)  d_in[25];
    float* out = (float*)d_out;

    float *pZ;
    cudaGetSymbolAddress((void**)&pZ, g_Z);

    cudaFuncSetAttribute(scan_kernel,
                         cudaFuncAttributeMaxDynamicSharedMemorySize, SMEM_BYTES);

    // 1. prep
    prep_kernel<<<(TSTEPS * HD + 255) / 256, 256>>>(times, W_noise, b_noise, mask);

    // 2. all independent prolog GEMMs in one wide launch
    stageA_kernel<<<1040, 256>>>(W_emb, Wf1, Wf2, W_out, b_out, Wg1, bg1,
                                 coeffs, W_init, b_init, bf2, b_emb, bf1);

    // 3. dependent prolog GEMMs
    stageB_kernel<<<160, 256>>>(W_X, b_X, Wg2, bg2);

    // 4. P[t] = a[:,t,:] @ M + cvec  (fully parallel over t)
    kernel_P<<<dim3(8, 8, TSTEPS), 256>>>(coeffs);

    // 5. entire 199-step scan in ONE persistent kernel
    scan_kernel<<<RG * GROUP_CTAS, 256, SMEM_BYTES>>>(noise);

    // 6. decode straight into (b,t,d) layout
    gemm_generic<<<dim3(2, 1600), 256>>>(pZ, HD, W_dec, DOUT, b_dec, 0,
                                         out, DOUT, TTOT * BSZ, DOUT, HD,
                                         ACT_DECODE);

    // 7. classifier logits
    cls_kernel<<<BSZ, 320>>>(W_cls, b_cls, out + (size_t)TTOT * BSZ * DOUT);
}

// round 15
// speedup vs baseline: 4.1708x; 1.3326x over previous
#include <cuda_runtime.h>
#include <math.h>

// Problem constants
#define TSTEPS 199
#define TTOT   200
#define BSZ    256
#define HD     512
#define BH     (BSZ*HD)        // 131072
#define DIN    64
#define DOUT   64
#define NCLS   10
#define LIPC   0.909f

#define ACT_NONE   0
#define ACT_LIP    1
#define ACT_DECODE 2

#define RG         8    // row groups (32 rows each)
#define GROUP_CTAS 16   // col CTAs per group (32 cols each)

#define KAUG  576                      // 512 (y) + 64 (a_t) augmented K for GEMM1
#define APAD  580                      // A row stride (580 mod 32 == 4 -> conflict-free)
#define WYPAD 580                      // augmented weight col stride
#define WOPAD 516                      // W2o col stride
#define SMEM_FLOATS (32*(WYPAD + WOPAD + APAD))
#define SMEM_BYTES  (SMEM_FLOATS*4)    // 214528 bytes

// ---------------- scratch (static device globals; no allocation) ----------------
__device__ __align__(256) float g_Z[TTOT*BH];              // trajectory   ~105MB
__device__ __align__(256) float g_h[BH];
__device__ __align__(256) float g_Wyf[HD*HD];              // W_emb_y @ Wf1
__device__ __align__(256) float g_W2o[HD*HD];              // Wf2 @ W_out
__device__ __align__(256) float g_E[HD*HD];                // W_emb_x @ Wf1
__device__ __align__(256) float g_b2o[HD];                 // bf2 @ W_out + b_out
__device__ __align__(256) float g_bvec1[HD];               // b_emb @ Wf1 + bf1
__device__ __align__(256) float g_M[DIN*HD];               // W_X @ E
__device__ __align__(256) float g_tt[TSTEPS*HD];
__device__ __align__(256) float g_G1[TSTEPS*HD];
__device__ __align__(256) float g_gt[TSTEPS*HD];
__device__ __align__(256) float g_cvec[HD];
__device__ float g_dts[TSTEPS];
__device__ float g_sqdts[TSTEPS];
__device__ int   g_lastidx[BSZ];
__device__ unsigned g_barctr[RG];

__device__ __forceinline__ float lipswish(float x) {
    return LIPC * x / (1.0f + __expf(-x));
}

// round fp32 -> tf32 (kept in 32-bit container)
__device__ __forceinline__ float tf32r(float x) {
    unsigned r;
    asm("cvt.rna.tf32.f32 %0, %1;" : "=r"(r) : "f"(x));
    return __uint_as_float(r);
}

// m16n8k8 tf32 MMA (row-major A, col-major B, fp32 accumulate)
__device__ __forceinline__ void mma_tf32(float& c0, float& c1, float& c2, float& c3,
                                         unsigned a0, unsigned a1, unsigned a2, unsigned a3,
                                         unsigned b0, unsigned b1)
{
    asm volatile(
        "mma.sync.aligned.m16n8k8.row.col.f32.tf32.tf32.f32 "
        "{%0,%1,%2,%3},{%4,%5,%6,%7},{%8,%9},{%0,%1,%2,%3};"
        : "+f"(c0), "+f"(c1), "+f"(c2), "+f"(c3)
        : "r"(a0), "r"(a1), "r"(a2), "r"(a3), "r"(b0), "r"(b1));
}

// ---------------- prep: tt, dts, sqrt(dts), last_idx, barrier counters -------
__global__ void prep_kernel(const float* __restrict__ times,
                            const float* __restrict__ W_noise,
                            const float* __restrict__ b_noise,
                            const int*   __restrict__ mask)
{
    int idx = blockIdx.x * blockDim.x + threadIdx.x;
    if (idx < TSTEPS * HD) {
        int t = idx >> 9, h = idx & (HD - 1);
        g_tt[idx] = times[t] * W_noise[h] + b_noise[h];
    }
    if (idx < TSTEPS) {
        float d = times[idx + 1] - times[idx];
        g_dts[idx] = d;
        g_sqdts[idx] = sqrtf(d);
    }
    if (idx < BSZ) {
        int s = 0;
        for (int t = 0; t < TTOT; t++) s += mask[idx * TTOT + t];
        int li = s - 1;
        if (li < 0) li = 0;
        if (li > TTOT - 1) li = TTOT - 1;
        g_lastidx[idx] = li;
    }
    if (idx < RG) g_barctr[idx] = 0u;   // reset group barriers every replay
}

// ---------------- 32x32 GEMM tile device function ----------------------------
__device__ __forceinline__
void gemm_tile(const float* __restrict__ A, int lda,
               const float* __restrict__ B, int ldb,
               const float* __restrict__ bias, int bias_stride,
               float* __restrict__ C, int ldc,
               int M, int N, int K, int act, int tileX, int tileY,
               float As[32][33], float Bs[32][33])
{
    int tid = threadIdx.x;
    int tx = tid & 15, ty = tid >> 4;
    int rowBase = tileY * 32;
    int colBase = tileX * 32;

    float acc00 = 0.f, acc01 = 0.f, acc10 = 0.f, acc11 = 0.f;

    for (int k0 = 0; k0 < K; k0 += 32) {
        #pragma unroll
        for (int i = 0; i < 4; i++) {
            int idx = tid + i * 256;
            int r = idx >> 5, c = idx & 31;
            int ar = rowBase + r, ac = k0 + c;
            As[r][c] = (ar < M && ac < K) ? A[(size_t)ar * lda + ac] : 0.f;
            int br = k0 + r, bc = colBase + c;
            Bs[r][c] = (br < K && bc < N) ? B[(size_t)br * ldb + bc] : 0.f;
        }
        __syncthreads();
        #pragma unroll
        for (int kk = 0; kk < 32; kk++) {
            float a0 = As[ty][kk], a1 = As[ty + 16][kk];
            float b0 = Bs[kk][tx], b1 = Bs[kk][tx + 16];
            acc00 = fmaf(a0, b0, acc00);
            acc01 = fmaf(a0, b1, acc01);
            acc10 = fmaf(a1, b0, acc10);
            acc11 = fmaf(a1, b1, acc11);
        }
        __syncthreads();
    }

    int r0 = rowBase + ty, r1 = r0 + 16;
    int c0 = colBase + tx, c1 = c0 + 16;

    #pragma unroll
    for (int i = 0; i < 4; i++) {
        int r = (i & 2) ? r1 : r0;
        int c = (i & 1) ? c1 : c0;
        float v = (i == 0) ? acc00 : (i == 1) ? acc01 : (i == 2) ? acc10 : acc11;
        if (r < M && c < N) {
            if (bias) v += bias[(size_t)r * bias_stride + c];
            if (act == ACT_LIP) v = lipswish(v);
            if (act == ACT_DECODE) {
                C[((size_t)(r & 255) * TTOT + (r >> 8)) * DOUT + c] = v;
            } else {
                C[(size_t)r * ldc + c] = v;
            }
        }
    }
}

__global__ void gemm_generic(const float* __restrict__ A, int lda,
                             const float* __restrict__ B, int ldb,
                             const float* __restrict__ bias, int bias_stride,
                             float* __restrict__ C, int ldc,
                             int M, int N, int K, int act)
{
    __shared__ float As[32][33];
    __shared__ float Bs[32][33];
    gemm_tile(A, lda, B, ldb, bias, bias_stride, C, ldc, M, N, K, act,
              blockIdx.x, blockIdx.y, As, Bs);
}

// ---------------- stage A: all independent prolog GEMMs in one launch --------
__global__ void stageA_kernel(const float* __restrict__ W_emb,
                              const float* __restrict__ Wf1,
                              const float* __restrict__ Wf2,
                              const float* __restrict__ W_out,
                              const float* __restrict__ b_out,
                              const float* __restrict__ Wg1,
                              const float* __restrict__ bg1,
                              const float* __restrict__ coeffs,
                              const float* __restrict__ W_init,
                              const float* __restrict__ b_init,
                              const float* __restrict__ bf2,
                              const float* __restrict__ b_emb,
                              const float* __restrict__ bf1)
{
    __shared__ float As[32][33];
    __shared__ float Bs[32][33];
    int b = blockIdx.x;
    if (b < 256) {
        gemm_tile(W_emb, HD, Wf1, HD, nullptr, 0, g_Wyf, HD,
                  HD, HD, HD, ACT_NONE, b & 15, b >> 4, As, Bs);
    } else if (b < 512) {
        int l = b - 256;
        gemm_tile(W_emb + (size_t)HD * HD, HD, Wf1, HD, nullptr, 0, g_E, HD,
                  HD, HD, HD, ACT_NONE, l & 15, l >> 4, As, Bs);
    } else if (b < 768) {
        int l = b - 512;
        gemm_tile(Wf2, HD, W_out, HD, nullptr, 0, g_W2o, HD,
                  HD, HD, HD, ACT_NONE, l & 15, l >> 4, As, Bs);
    } else if (b < 880) {
        int l = b - 768;
        gemm_tile(g_tt, HD, Wg1, HD, bg1, 0, g_G1, HD,
                  TSTEPS, HD, HD, ACT_LIP, l & 15, l >> 4, As, Bs);
    } else if (b < 1008) {
        int l = b - 880;
        gemm_tile(coeffs, TSTEPS * 256, W_init, HD, b_init, 0, g_Z, HD,
                  BSZ, HD, DIN, ACT_NONE, l & 15, l >> 4, As, Bs);
    } else if (b < 1024) {
        int l = b - 1008;
        gemm_tile(bf2, HD, W_out, HD, b_out, 0, g_b2o, HD,
                  1, HD, HD, ACT_NONE, l, 0, As, Bs);
    } else {
        int l = b - 1024;
        gemm_tile(b_emb, HD, Wf1, HD, bf1, 0, g_bvec1, HD,
                  1, HD, HD, ACT_NONE, l, 0, As, Bs);
    }
}

// ---------------- stage B: dependent prolog GEMMs ----------------------------
__global__ void stageB_kernel(const float* __restrict__ W_X,
                              const float* __restrict__ b_X,
                              const float* __restrict__ Wg2,
                              const float* __restrict__ bg2)
{
    __shared__ float As[32][33];
    __shared__ float Bs[32][33];
    int b = blockIdx.x;
    if (b < 32) {
        gemm_tile(W_X, HD, g_E, HD, nullptr, 0, g_M, HD,
                  DIN, HD, HD, ACT_NONE, b & 15, b >> 4, As, Bs);
    } else if (b < 48) {
        int l = b - 32;
        gemm_tile(b_X, HD, g_E, HD, g_bvec1, 0, g_cvec, HD,
                  1, HD, HD, ACT_NONE, l, 0, As, Bs);
    } else {
        int l = b - 48;
        gemm_tile(g_G1, HD, Wg2, HD, bg2, 0, g_gt, HD,
                  TSTEPS, HD, HD, ACT_NONE, l & 15, l >> 4, As, Bs);
    }
}

// ---------------- group-local barrier: release-add + acquire-poll ------------
__device__ __forceinline__ void group_barrier(int g, unsigned target)
{
    __syncthreads();
    if (threadIdx.x == 0) {
        unsigned* ctr = &g_barctr[g];
        asm volatile("red.release.gpu.global.add.u32 [%0], 1;"
                     :: "l"(ctr) : "memory");
        unsigned v;
        do {
            asm volatile("ld.acquire.gpu.global.u32 %0, [%1];"
                         : "=r"(v) : "l"(ctr) : "memory");
        } while (v < target);
    }
    __syncthreads();
}

// ---------------- persistent scan kernel (tensor-core mainloop) --------------
// 128 CTAs = 8 row-groups x 16 col-CTAs. Per step:
//   GEMM1: h = lipswish([y ; a_t] @ [Wyf ; M] + cvec)   (K = 576, tf32 mma)
//   GEMM2: y' = y + (h @ W2o + b2o)*dt + gt*noise*sqdt  (K = 512, tf32 mma)
// Warp w: rows [16*(w&1), +16), cols [8*(w>>2... (w>>1)*8, +8) of the 32x32 tile.
__global__ void __launch_bounds__(256, 1)
scan_kernel(const float* __restrict__ noise, const float* __restrict__ coeffs)
{
    extern __shared__ float smem[];
    float* sWy = smem;                       // [32 cols][WYPAD] col-major, K=576
    float* sWo = smem + 32 * WYPAD;          // [32 cols][WOPAD] col-major, K=512
    float* sA  = sWo + 32 * WOPAD;           // [32 rows][APAD]  row-major, K<=576
    const unsigned* uWy = (const unsigned*)sWy;
    const unsigned* uWo = (const unsigned*)sWo;
    const unsigned* uA  = (const unsigned*)sA;

    const int g    = blockIdx.x >> 4;
    const int c0   = (blockIdx.x & 15) << 5;
    const int r0   = g << 5;
    const int tid  = threadIdx.x;
    const int lane = tid & 31;
    const int w    = tid >> 5;
    const int wrow = w & 1;                  // 16-row half
    const int wcol = w >> 1;                 // 8-col block (0..3)
    const int gq   = lane >> 2;              // 0..7
    const int t4   = lane & 3;               // 0..3

    // fragment source rows/cols (local)
    const int lrA = wrow * 16 + gq;          // A frag row 0
    const int lrB = lrA + 8;                 // A frag row 1
    const int lcB = wcol * 8 + gq;           // B frag col
    // output coords (global)
    const int rA = r0 + lrA, rB = r0 + lrB;
    const int cA = c0 + wcol * 8 + 2 * t4;   // covers (cA, cA+1)

    // ---- persistent weights: transpose + tf32-round (once) ----
    {
        int col = tid & 31;
        int kb  = tid >> 5;
        #pragma unroll 4
        for (int it = 0; it < 64; it++) {
            int k = kb + (it << 3);
            sWy[col * WYPAD + k] = tf32r(g_Wyf[(size_t)k * HD + c0 + col]);
            sWo[col * WOPAD + k] = tf32r(g_W2o[(size_t)k * HD + c0 + col]);
        }
        #pragma unroll
        for (int it = 0; it < 8; it++) {
            int km = kb + (it << 3);
            sWy[col * WYPAD + 512 + km] = tf32r(g_M[(size_t)km * HD + c0 + col]);
        }
    }

    const float2 cv = *(const float2*)(g_cvec + cA);
    const float2 b2 = *(const float2*)(g_b2o + cA);

    unsigned target = GROUP_CTAS;

    for (int t = 0; t < TSTEPS; t++) {
        const float* Zt = g_Z + (size_t)t * BH;
        float*       Zn = g_Z + (size_t)(t + 1) * BH;

        // ---- fill A: y rows (tf32-rounded) + a_t block ----
        {
            const float* src = Zt + (size_t)r0 * HD;
            #pragma unroll 4
            for (int it = 0; it < 16; it++) {
                int f4 = tid + (it << 8);
                int row = f4 >> 7, c4 = (f4 & 127) << 2;
                float4 v = *(const float4*)(src + (size_t)row * HD + c4);
                v.x = tf32r(v.x); v.y = tf32r(v.y);
                v.z = tf32r(v.z); v.w = tf32r(v.w);
                *(float4*)(sA + row * APAD + c4) = v;
            }
            #pragma unroll
            for (int it = 0; it < 2; it++) {
                int f4 = tid + (it << 8);
                int row = f4 >> 4, c4 = (f4 & 15) << 2;
                float4 v = *(const float4*)(coeffs +
                            ((size_t)(r0 + row) * TSTEPS + t) * 256 + c4);
                v.x = tf32r(v.x); v.y = tf32r(v.y);
                v.z = tf32r(v.z); v.w = tf32r(v.w);
                *(float4*)(sA + row * APAD + 512 + c4) = v;
            }
        }
        __syncthreads();

        // ---- GEMM1: 72 k8 steps, two interleaved accumulator sets ----
        float e0 = 0.f, e1 = 0.f, e2 = 0.f, e3 = 0.f;
        float o0 = 0.f, o1 = 0.f, o2 = 0.f, o3 = 0.f;
        {
            const unsigned* pa0 = uA + lrA * APAD + t4;
            const unsigned* pa1 = uA + lrB * APAD + t4;
            const unsigned* pb  = uWy + lcB * WYPAD + t4;
            #pragma unroll 4
            for (int k8 = 0; k8 < 72; k8 += 2) {
                int k = k8 << 3;
                mma_tf32(e0, e1, e2, e3,
                         pa0[k], pa1[k], pa0[k + 4], pa1[k + 4],
                         pb[k], pb[k + 4]);
                mma_tf32(o0, o1, o2, o3,
                         pa0[k + 8], pa1[k + 8], pa0[k + 12], pa1[k + 12],
                         pb[k + 8], pb[k + 12]);
            }
        }
        {
            float d0 = e0 + o0, d1 = e1 + o1, d2 = e2 + o2, d3 = e3 + o3;
            float2 h0, h1;
            h0.x = lipswish(d0 + cv.x); h0.y = lipswish(d1 + cv.y);
            h1.x = lipswish(d2 + cv.x); h1.y = lipswish(d3 + cv.y);
            *(float2*)(g_h + (size_t)rA * HD + cA) = h0;
            *(float2*)(g_h + (size_t)rB * HD + cA) = h1;
        }

        // prefetch GEMM2 epilogue operands BEFORE the barrier (hide DRAM)
        const float dt = g_dts[t], sq = g_sqdts[t];
        float2 gt2 = *(const float2*)(g_gt + t * HD + cA);
        const float* Nt = noise + (size_t)t * BH;
        float2 nA = *(const float2*)(Nt + (size_t)rA * HD + cA);
        float2 nB = *(const float2*)(Nt + (size_t)rB * HD + cA);
        float2 zA = *(const float2*)(Zt + (size_t)rA * HD + cA);
        float2 zB = *(const float2*)(Zt + (size_t)rB * HD + cA);

        group_barrier(g, target); target += GROUP_CTAS;

        // ---- fill A = h (tf32-rounded) ----
        {
            const float* src = g_h + (size_t)r0 * HD;
            #pragma unroll 4
            for (int it = 0; it < 16; it++) {
                int f4 = tid + (it << 8);
                int row = f4 >> 7, c4 = (f4 & 127) << 2;
                float4 v = *(const float4*)(src + (size_t)row * HD + c4);
                v.x = tf32r(v.x); v.y = tf32r(v.y);
                v.z = tf32r(v.z); v.w = tf32r(v.w);
                *(float4*)(sA + row * APAD + c4) = v;
            }
        }
        __syncthreads();

        // ---- GEMM2: 64 k8 steps ----
        e0 = e1 = e2 = e3 = 0.f;
        o0 = o1 = o2 = o3 = 0.f;
        {
            const unsigned* pa0 = uA + lrA * APAD + t4;
            const unsigned* pa1 = uA + lrB * APAD + t4;
            const unsigned* pb  = uWo + lcB * WOPAD + t4;
            #pragma unroll 4
            for (int k8 = 0; k8 < 64; k8 += 2) {
                int k = k8 << 3;
                mma_tf32(e0, e1, e2, e3,
                         pa0[k], pa1[k], pa0[k + 4], pa1[k + 4],
                         pb[k], pb[k + 4]);
                mma_tf32(o0, o1, o2, o3,
                         pa0[k + 8], pa1[k + 8], pa0[k + 12], pa1[k + 12],
                         pb[k + 8], pb[k + 12]);
            }
        }
        {
            float d0 = e0 + o0, d1 = e1 + o1, d2 = e2 + o2, d3 = e3 + o3;
            float gx = gt2.x * sq, gy = gt2.y * sq;
            float2 w0, w1;
            w0.x = zA.x + (d0 + b2.x) * dt + gx * nA.x;
            w0.y = zA.y + (d1 + b2.y) * dt + gy * nA.y;
            w1.x = zB.x + (d2 + b2.x) * dt + gx * nB.x;
            w1.y = zB.y + (d3 + b2.y) * dt + gy * nB.y;
            *(float2*)(Zn + (size_t)rA * HD + cA) = w0;
            *(float2*)(Zn + (size_t)rB * HD + cA) = w1;
        }
        group_barrier(g, target); target += GROUP_CTAS;
    }
}

// ---------------- classifier: logits = z[last_idx] @ W_cls + b_cls ----------
__global__ void cls_kernel(const float* __restrict__ W_cls,
                           const float* __restrict__ b_cls,
                           float* __restrict__ logits)
{
    int b = blockIdx.x;
    int w = threadIdx.x >> 5, lane = threadIdx.x & 31;
    if (w >= NCLS) return;
    int li = g_lastidx[b];
    const float* z = g_Z + ((size_t)li * BSZ + b) * HD;
    float s = 0.f;
    for (int h = lane; h < HD; h += 32)
        s += z[h] * W_cls[h * NCLS + w];
    #pragma unroll
    for (int o = 16; o; o >>= 1) s += __shfl_down_sync(0xffffffffu, s, o);
    if (lane == 0) logits[b * NCLS + w] = s + b_cls[w];
}

// ---------------- launch ----------------
extern "C" void kernel_launch(void* const* d_in, const int* in_sizes, int n_in,
                              void* d_out, int out_size)
{
    const float* coeffs  = (const float*)d_in[0];
    const float* times   = (const float*)d_in[1];
    const float* noise   = (const float*)d_in[2];
    const float* W_X     = (const float*)d_in[3];
    const float* b_X     = (const float*)d_in[4];
    const float* W_emb   = (const float*)d_in[5];
    const float* b_emb   = (const float*)d_in[6];
    const float* Wf1     = (const float*)d_in[7];
    const float* bf1     = (const float*)d_in[8];
    const float* Wf2     = (const float*)d_in[9];
    const float* bf2     = (const float*)d_in[10];
    const float* W_out   = (const float*)d_in[11];
    const float* b_out   = (const float*)d_in[12];
    const float* W_noise = (const float*)d_in[13];
    const float* b_noise = (const float*)d_in[14];
    const float* Wg1     = (const float*)d_in[15];
    const float* bg1     = (const float*)d_in[16];
    const float* Wg2     = (const float*)d_in[17];
    const float* bg2     = (const float*)d_in[18];
    const float* W_init  = (const float*)d_in[19];
    const float* b_init  = (const float*)d_in[20];
    const float* W_dec   = (const float*)d_in[21];
    const float* b_dec   = (const float*)d_in[22];
    const float* W_cls   = (const float*)d_in[23];
    const float* b_cls   = (const float*)d_in[24];
    const int*   mask    = (const int*)  d_in[25];
    float* out = (float*)d_out;

    float* pZ;
    cudaGetSymbolAddress((void**)&pZ, g_Z);

    cudaFuncSetAttribute(scan_kernel,
                         cudaFuncAttributeMaxDynamicSharedMemorySize, SMEM_BYTES);

    // 1. prep
    prep_kernel<<<(TSTEPS * HD + 255) / 256, 256>>>(times, W_noise, b_noise, mask);

    // 2. independent prolog GEMMs (one wide launch)
    stageA_kernel<<<1040, 256>>>(W_emb, Wf1, Wf2, W_out, b_out, Wg1, bg1,
                                 coeffs, W_init, b_init, bf2, b_emb, bf1);

    // 3. dependent prolog GEMMs (M, cvec, gt)
    stageB_kernel<<<160, 256>>>(W_X, b_X, Wg2, bg2);

    // 4. full 199-step scan, tensor-core mainloop, P fused via K-augmentation
    scan_kernel<<<RG * GROUP_CTAS, 256, SMEM_BYTES>>>(noise, coeffs);

    // 5. decode straight into (b,t,d) layout
    gemm_generic<<<dim3(2, 1600), 256>>>(pZ, HD, W_dec, DOUT, b_dec, 0,
                                         out, DOUT, TTOT * BSZ, DOUT, HD,
                                         ACT_DECODE);

    // 6. classifier logits
    cls_kernel<<<BSZ, 320>>>(W_cls, b_cls, out + (size_t)TTOT * BSZ * DOUT);
}

// round 16
// speedup vs baseline: 5.4623x; 1.3097x over previous
#include <cuda_runtime.h>
#include <math.h>

// Problem constants
#define TSTEPS 199
#define TTOT   200
#define BSZ    256
#define HD     512
#define BH     (BSZ*HD)        // 131072
#define DIN    64
#define DOUT   64
#define NCLS   10
#define LIPC   0.909f

#define ACT_NONE   0
#define ACT_LIP    1
#define ACT_DECODE 2

#define RG         8    // row groups (32 rows each)
#define GROUP_CTAS 16   // col CTAs per group (32 cols each)

// permuted-k layout: p(k) = (k&3)*KBLK + (k>>2); row stride = 4*KBLK
#define KBLK  148                     // (KBLK/4) mod 8 == 5 -> t4 phases distinct
#define RSTR  (4*KBLK)                // 592; (RSTR/4) mod 8 == 4 -> rows distinct
#define SMEM_FLOATS (3*32*RSTR)       // sWy + sWo + sA
#define SMEM_BYTES  (SMEM_FLOATS*4)   // 227328 bytes

// ---------------- scratch (static device globals; no allocation) ----------------
__device__ __align__(256) float g_Z[TTOT*BH];              // trajectory   ~105MB
__device__ __align__(256) float g_h[BH];
__device__ __align__(256) float g_Wyf[HD*HD];              // W_emb_y @ Wf1
__device__ __align__(256) float g_W2o[HD*HD];              // Wf2 @ W_out
__device__ __align__(256) float g_E[HD*HD];                // W_emb_x @ Wf1
__device__ __align__(256) float g_b2o[HD];                 // bf2 @ W_out + b_out
__device__ __align__(256) float g_bvec1[HD];               // b_emb @ Wf1 + bf1
__device__ __align__(256) float g_M[DIN*HD];               // W_X @ E
__device__ __align__(256) float g_tt[TSTEPS*HD];
__device__ __align__(256) float g_G1[TSTEPS*HD];
__device__ __align__(256) float g_gt[TSTEPS*HD];
__device__ __align__(256) float g_cvec[HD];
__device__ float g_dts[TSTEPS];
__device__ float g_sqdts[TSTEPS];
__device__ int   g_lastidx[BSZ];
__device__ __align__(256) unsigned g_barctr[RG*32];        // 128B stride per group

__device__ __forceinline__ float lipswish(float x) {
    return LIPC * x / (1.0f + __expf(-x));
}

// round fp32 -> tf32 (kept in 32-bit container)
__device__ __forceinline__ float tf32r(float x) {
    unsigned r;
    asm("cvt.rna.tf32.f32 %0, %1;" : "=r"(r) : "f"(x));
    return __uint_as_float(r);
}

// m16n8k8 tf32 MMA (row-major A, col-major B, fp32 accumulate)
__device__ __forceinline__ void mma_tf32(float& c0, float& c1, float& c2, float& c3,
                                         unsigned a0, unsigned a1, unsigned a2, unsigned a3,
                                         unsigned b0, unsigned b1)
{
    asm volatile(
        "mma.sync.aligned.m16n8k8.row.col.f32.tf32.tf32.f32 "
        "{%0,%1,%2,%3},{%4,%5,%6,%7},{%8,%9},{%0,%1,%2,%3};"
        : "+f"(c0), "+f"(c1), "+f"(c2), "+f"(c3)
        : "r"(a0), "r"(a1), "r"(a2), "r"(a3), "r"(b0), "r"(b1));
}

// ---------------- prep ----------------
__global__ void prep_kernel(const float* __restrict__ times,
                            const float* __restrict__ W_noise,
                            const float* __restrict__ b_noise,
                            const int*   __restrict__ mask)
{
    int idx = blockIdx.x * blockDim.x + threadIdx.x;
    if (idx < TSTEPS * HD) {
        int t = idx >> 9, h = idx & (HD - 1);
        g_tt[idx] = times[t] * W_noise[h] + b_noise[h];
    }
    if (idx < TSTEPS) {
        float d = times[idx + 1] - times[idx];
        g_dts[idx] = d;
        g_sqdts[idx] = sqrtf(d);
    }
    if (idx < BSZ) {
        int s = 0;
        for (int t = 0; t < TTOT; t++) s += mask[idx * TTOT + t];
        int li = s - 1;
        if (li < 0) li = 0;
        if (li > TTOT - 1) li = TTOT - 1;
        g_lastidx[idx] = li;
    }
    if (idx < RG * 32) g_barctr[idx] = 0u;   // reset padded barriers every replay
}

// ---------------- 32x32 GEMM tile device function ----------------------------
__device__ __forceinline__
void gemm_tile(const float* __restrict__ A, int lda,
               const float* __restrict__ B, int ldb,
               const float* __restrict__ bias, int bias_stride,
               float* __restrict__ C, int ldc,
               int M, int N, int K, int act, int tileX, int tileY,
               float As[32][33], float Bs[32][33])
{
    int tid = threadIdx.x;
    int tx = tid & 15, ty = tid >> 4;
    int rowBase = tileY * 32;
    int colBase = tileX * 32;

    float acc00 = 0.f, acc01 = 0.f, acc10 = 0.f, acc11 = 0.f;

    for (int k0 = 0; k0 < K; k0 += 32) {
        #pragma unroll
        for (int i = 0; i < 4; i++) {
            int idx = tid + i * 256;
            int r = idx >> 5, c = idx & 31;
            int ar = rowBase + r, ac = k0 + c;
            As[r][c] = (ar < M && ac < K) ? A[(size_t)ar * lda + ac] : 0.f;
            int br = k0 + r, bc = colBase + c;
            Bs[r][c] = (br < K && bc < N) ? B[(size_t)br * ldb + bc] : 0.f;
        }
        __syncthreads();
        #pragma unroll
        for (int kk = 0; kk < 32; kk++) {
            float a0 = As[ty][kk], a1 = As[ty + 16][kk];
            float b0 = Bs[kk][tx], b1 = Bs[kk][tx + 16];
            acc00 = fmaf(a0, b0, acc00);
            acc01 = fmaf(a0, b1, acc01);
            acc10 = fmaf(a1, b0, acc10);
            acc11 = fmaf(a1, b1, acc11);
        }
        __syncthreads();
    }

    int r0 = rowBase + ty, r1 = r0 + 16;
    int c0 = colBase + tx, c1 = c0 + 16;

    #pragma unroll
    for (int i = 0; i < 4; i++) {
        int r = (i & 2) ? r1 : r0;
        int c = (i & 1) ? c1 : c0;
        float v = (i == 0) ? acc00 : (i == 1) ? acc01 : (i == 2) ? acc10 : acc11;
        if (r < M && c < N) {
            if (bias) v += bias[(size_t)r * bias_stride + c];
            if (act == ACT_LIP) v = lipswish(v);
            if (act == ACT_DECODE) {
                C[((size_t)(r & 255) * TTOT + (r >> 8)) * DOUT + c] = v;
            } else {
                C[(size_t)r * ldc + c] = v;
            }
        }
    }
}

__global__ void gemm_generic(const float* __restrict__ A, int lda,
                             const float* __restrict__ B, int ldb,
                             const float* __restrict__ bias, int bias_stride,
                             float* __restrict__ C, int ldc,
                             int M, int N, int K, int act)
{
    __shared__ float As[32][33];
    __shared__ float Bs[32][33];
    gemm_tile(A, lda, B, ldb, bias, bias_stride, C, ldc, M, N, K, act,
              blockIdx.x, blockIdx.y, As, Bs);
}

// ---------------- stage A: all independent prolog GEMMs in one launch --------
__global__ void stageA_kernel(const float* __restrict__ W_emb,
                              const float* __restrict__ Wf1,
                              const float* __restrict__ Wf2,
                              const float* __restrict__ W_out,
                              const float* __restrict__ b_out,
                              const float* __restrict__ Wg1,
                              const float* __restrict__ bg1,
                              const float* __restrict__ coeffs,
                              const float* __restrict__ W_init,
                              const float* __restrict__ b_init,
                              const float* __restrict__ bf2,
                              const float* __restrict__ b_emb,
                              const float* __restrict__ bf1)
{
    __shared__ float As[32][33];
    __shared__ float Bs[32][33];
    int b = blockIdx.x;
    if (b < 256) {
        gemm_tile(W_emb, HD, Wf1, HD, nullptr, 0, g_Wyf, HD,
                  HD, HD, HD, ACT_NONE, b & 15, b >> 4, As, Bs);
    } else if (b < 512) {
        int l = b - 256;
        gemm_tile(W_emb + (size_t)HD * HD, HD, Wf1, HD, nullptr, 0, g_E, HD,
                  HD, HD, HD, ACT_NONE, l & 15, l >> 4, As, Bs);
    } else if (b < 768) {
        int l = b - 512;
        gemm_tile(Wf2, HD, W_out, HD, nullptr, 0, g_W2o, HD,
                  HD, HD, HD, ACT_NONE, l & 15, l >> 4, As, Bs);
    } else if (b < 880) {
        int l = b - 768;
        gemm_tile(g_tt, HD, Wg1, HD, bg1, 0, g_G1, HD,
                  TSTEPS, HD, HD, ACT_LIP, l & 15, l >> 4, As, Bs);
    } else if (b < 1008) {
        int l = b - 880;
        gemm_tile(coeffs, TSTEPS * 256, W_init, HD, b_init, 0, g_Z, HD,
                  BSZ, HD, DIN, ACT_NONE, l & 15, l >> 4, As, Bs);
    } else if (b < 1024) {
        int l = b - 1008;
        gemm_tile(bf2, HD, W_out, HD, b_out, 0, g_b2o, HD,
                  1, HD, HD, ACT_NONE, l, 0, As, Bs);
    } else {
        int l = b - 1024;
        gemm_tile(b_emb, HD, Wf1, HD, bf1, 0, g_bvec1, HD,
                  1, HD, HD, ACT_NONE, l, 0, As, Bs);
    }
}

// ---------------- stage B: dependent prolog GEMMs ----------------------------
__global__ void stageB_kernel(const float* __restrict__ W_X,
                              const float* __restrict__ b_X,
                              const float* __restrict__ Wg2,
                              const float* __restrict__ bg2)
{
    __shared__ float As[32][33];
    __shared__ float Bs[32][33];
    int b = blockIdx.x;
    if (b < 32) {
        gemm_tile(W_X, HD, g_E, HD, nullptr, 0, g_M, HD,
                  DIN, HD, HD, ACT_NONE, b & 15, b >> 4, As, Bs);
    } else if (b < 48) {
        int l = b - 32;
        gemm_tile(b_X, HD, g_E, HD, g_bvec1, 0, g_cvec, HD,
                  1, HD, HD, ACT_NONE, l, 0, As, Bs);
    } else {
        int l = b - 48;
        gemm_tile(g_G1, HD, Wg2, HD, bg2, 0, g_gt, HD,
                  TSTEPS, HD, HD, ACT_NONE, l & 15, l >> 4, As, Bs);
    }
}

// ---------------- group-local barrier (padded counters, one line per group) --
__device__ __forceinline__ void group_barrier(int g, unsigned target)
{
    __syncthreads();
    if (threadIdx.x == 0) {
        unsigned* ctr = &g_barctr[g * 32];
        asm volatile("red.release.gpu.global.add.u32 [%0], 1;"
                     :: "l"(ctr) : "memory");
        unsigned v;
        do {
            asm volatile("ld.acquire.gpu.global.u32 %0, [%1];"
                         : "=r"(v) : "l"(ctr) : "memory");
        } while (v < target);
    }
    __syncthreads();
}

// ---------------- persistent scan kernel (tensor-core, permuted-k smem) ------
// GEMM1: h = lipswish([y ; a_t] @ [Wyf ; M] + cvec)   (K = 576)
// GEMM2: y' = y + (h @ W2o + b2o)*dt + gt*noise*sqdt  (K = 512)
__global__ void __launch_bounds__(256, 1)
scan_kernel(const float* __restrict__ noise, const float* __restrict__ coeffs)
{
    extern __shared__ float smem[];
    float* sWy = smem;                       // [32 cols][RSTR] permuted-k, K=576
    float* sWo = smem + 32 * RSTR;           // [32 cols][RSTR] permuted-k, K=512
    float* sA  = sWo + 32 * RSTR;            // [32 rows][RSTR] permuted-k

    const int g    = blockIdx.x >> 4;
    const int c0   = (blockIdx.x & 15) << 5;
    const int r0   = g << 5;
    const int tid  = threadIdx.x;
    const int lane = tid & 31;
    const int w    = tid >> 5;
    const int wrow = w & 1;
    const int wcol = w >> 1;
    const int gq   = lane >> 2;
    const int t4   = lane & 3;

    const int lrA = wrow * 16 + gq;
    const int lrB = lrA + 8;
    const int lcB = wcol * 8 + gq;
    const int rA = r0 + lrA, rB = r0 + lrB;
    const int cA = c0 + wcol * 8 + 2 * t4;

    // ---- persistent weights: transpose + permute + tf32 (once) ----
    {
        int col = tid & 31;
        int kb  = tid >> 5;
        #pragma unroll 4
        for (int it = 0; it < 64; it++) {
            int k = kb + (it << 3);
            int p = (k & 3) * KBLK + (k >> 2);
            sWy[col * RSTR + p] = tf32r(g_Wyf[(size_t)k * HD + c0 + col]);
            sWo[col * RSTR + p] = tf32r(g_W2o[(size_t)k * HD + c0 + col]);
        }
        #pragma unroll
        for (int it = 0; it < 8; it++) {
            int km = kb + (it << 3);
            int k = 512 + km;
            int p = (k & 3) * KBLK + (k >> 2);
            sWy[col * RSTR + p] = tf32r(g_M[(size_t)km * HD + c0 + col]);
        }
    }

    const float2 cv = *(const float2*)(g_cvec + cA);
    const float2 b2 = *(const float2*)(g_b2o + cA);

    const unsigned* a0p = (const unsigned*)(sA  + lrA * RSTR + t4 * KBLK);
    const unsigned* a1p = (const unsigned*)(sA  + lrB * RSTR + t4 * KBLK);
    const unsigned* byp = (const unsigned*)(sWy + lcB * RSTR + t4 * KBLK);
    const unsigned* bop = (const unsigned*)(sWo + lcB * RSTR + t4 * KBLK);

    unsigned target = GROUP_CTAS;

    for (int t = 0; t < TSTEPS; t++) {
        const float* Zt = g_Z + (size_t)t * BH;
        float*       Zn = g_Z + (size_t)(t + 1) * BH;

        // ---- fill A: y rows (permuted scatter) + a_t block ----
        {
            const float* src = Zt + (size_t)r0 * HD;
            #pragma unroll 4
            for (int it = 0; it < 16; it++) {
                int f4 = tid + (it << 8);
                int row = f4 >> 7, q = f4 & 127;       // k = 4q .. 4q+3
                float4 v = *(const float4*)(src + (size_t)row * HD + (q << 2));
                float* d = sA + row * RSTR + q;
                d[0]        = tf32r(v.x);
                d[KBLK]     = tf32r(v.y);
                d[2 * KBLK] = tf32r(v.z);
                d[3 * KBLK] = tf32r(v.w);
            }
            #pragma unroll
            for (int it = 0; it < 2; it++) {
                int f4 = tid + (it << 8);
                int row = f4 >> 4, qq = f4 & 15;       // k = 512 + 4qq ..
                float4 v = *(const float4*)(coeffs +
                            ((size_t)(r0 + row) * TSTEPS + t) * 256 + (qq << 2));
                float* d = sA + row * RSTR + 128 + qq;
                d[0]        = tf32r(v.x);
                d[KBLK]     = tf32r(v.y);
                d[2 * KBLK] = tf32r(v.z);
                d[3 * KBLK] = tf32r(v.w);
            }
        }
        __syncthreads();

        // ---- GEMM1: 72 MMAs, 4 accumulator chains, LDS.128 frags ----
        float u0 = 0.f, u1 = 0.f, u2 = 0.f, u3 = 0.f;
        float v0 = 0.f, v1 = 0.f, v2 = 0.f, v3 = 0.f;
        float x0 = 0.f, x1 = 0.f, x2 = 0.f, x3 = 0.f;
        float y0 = 0.f, y1 = 0.f, y2 = 0.f, y3 = 0.f;
        {
            #pragma unroll
            for (int i = 0; i < 36; i += 2) {
                uint4 A0 = *(const uint4*)(a0p + 4 * i);
                uint4 A1 = *(const uint4*)(a1p + 4 * i);
                uint4 B0 = *(const uint4*)(byp + 4 * i);
                uint4 A2 = *(const uint4*)(a0p + 4 * i + 4);
                uint4 A3 = *(const uint4*)(a1p + 4 * i + 4);
                uint4 B1 = *(const uint4*)(byp + 4 * i + 4);
                mma_tf32(u0, u1, u2, u3, A0.x, A1.x, A0.y, A1.y, B0.x, B0.y);
                mma_tf32(v0, v1, v2, v3, A0.z, A1.z, A0.w, A1.w, B0.z, B0.w);
                mma_tf32(x0, x1, x2, x3, A2.x, A3.x, A2.y, A3.y, B1.x, B1.y);
                mma_tf32(y0, y1, y2, y3, A2.z, A3.z, A2.w, A3.w, B1.z, B1.w);
            }
        }
        {
            float d0 = (u0 + v0) + (x0 + y0);
            float d1 = (u1 + v1) + (x1 + y1);
            float d2 = (u2 + v2) + (x2 + y2);
            float d3 = (u3 + v3) + (x3 + y3);
            float2 h0, h1;
            h0.x = lipswish(d0 + cv.x); h0.y = lipswish(d1 + cv.y);
            h1.x = lipswish(d2 + cv.x); h1.y = lipswish(d3 + cv.y);
            *(float2*)(g_h + (size_t)rA * HD + cA) = h0;
            *(float2*)(g_h + (size_t)rB * HD + cA) = h1;
        }

        // prefetch GEMM2 epilogue operands BEFORE the barrier
        const float dt = g_dts[t], sq = g_sqdts[t];
        float2 gt2 = *(const float2*)(g_gt + t * HD + cA);
        const float* Nt = noise + (size_t)t * BH;
        float2 nA = *(const float2*)(Nt + (size_t)rA * HD + cA);
        float2 nB = *(const float2*)(Nt + (size_t)rB * HD + cA);
        float2 zA = *(const float2*)(Zt + (size_t)rA * HD + cA);
        float2 zB = *(const float2*)(Zt + (size_t)rB * HD + cA);

        group_barrier(g, target); target += GROUP_CTAS;

        // ---- fill A = h (permuted scatter) ----
        {
            const float* src = g_h + (size_t)r0 * HD;
            #pragma unroll 4
            for (int it = 0; it < 16; it++) {
                int f4 = tid + (it << 8);
                int row = f4 >> 7, q = f4 & 127;
                float4 v = *(const float4*)(src + (size_t)row * HD + (q << 2));
                float* d = sA + row * RSTR + q;
                d[0]        = tf32r(v.x);
                d[KBLK]     = tf32r(v.y);
                d[2 * KBLK] = tf32r(v.z);
                d[3 * KBLK] = tf32r(v.w);
            }
        }
        __syncthreads();

        // ---- GEMM2: 64 MMAs ----
        u0 = u1 = u2 = u3 = 0.f;
        v0 = v1 = v2 = v3 = 0.f;
        x0 = x1 = x2 = x3 = 0.f;
        y0 = y1 = y2 = y3 = 0.f;
        {
            #pragma unroll
            for (int i = 0; i < 32; i += 2) {
                uint4 A0 = *(const uint4*)(a0p + 4 * i);
                uint4 A1 = *(const uint4*)(a1p + 4 * i);
                uint4 B0 = *(const uint4*)(bop + 4 * i);
                uint4 A2 = *(const uint4*)(a0p + 4 * i + 4);
                uint4 A3 = *(const uint4*)(a1p + 4 * i + 4);
                uint4 B1 = *(const uint4*)(bop + 4 * i + 4);
                mma_tf32(u0, u1, u2, u3, A0.x, A1.x, A0.y, A1.y, B0.x, B0.y);
                mma_tf32(v0, v1, v2, v3, A0.z, A1.z, A0.w, A1.w, B0.z, B0.w);
                mma_tf32(x0, x1, x2, x3, A2.x, A3.x, A2.y, A3.y, B1.x, B1.y);
                mma_tf32(y0, y1, y2, y3, A2.z, A3.z, A2.w, A3.w, B1.z, B1.w);
            }
        }
        {
            float d0 = (u0 + v0) + (x0 + y0);
            float d1 = (u1 + v1) + (x1 + y1);
            float d2 = (u2 + v2) + (x2 + y2);
            float d3 = (u3 + v3) + (x3 + y3);
            float gx = gt2.x * sq, gy = gt2.y * sq;
            float2 w0, w1;
            w0.x = zA.x + (d0 + b2.x) * dt + gx * nA.x;
            w0.y = zA.y + (d1 + b2.y) * dt + gy * nA.y;
            w1.x = zB.x + (d2 + b2.x) * dt + gx * nB.x;
            w1.y = zB.y + (d3 + b2.y) * dt + gy * nB.y;
            *(float2*)(Zn + (size_t)rA * HD + cA) = w0;
            *(float2*)(Zn + (size_t)rB * HD + cA) = w1;
        }
        group_barrier(g, target); target += GROUP_CTAS;
    }
}

// ---------------- classifier ----------------
__global__ void cls_kernel(const float* __restrict__ W_cls,
                           const float* __restrict__ b_cls,
                           float* __restrict__ logits)
{
    int b = blockIdx.x;
    int w = threadIdx.x >> 5, lane = threadIdx.x & 31;
    if (w >= NCLS) return;
    int li = g_lastidx[b];
    const float* z = g_Z + ((size_t)li * BSZ + b) * HD;
    float s = 0.f;
    for (int h = lane; h < HD; h += 32)
        s += z[h] * W_cls[h * NCLS + w];
    #pragma unroll
    for (int o = 16; o; o >>= 1) s += __shfl_down_sync(0xffffffffu, s, o);
    if (lane == 0) logits[b * NCLS + w] = s + b_cls[w];
}

// ---------------- launch ----------------
extern "C" void kernel_launch(void* const* d_in, const int* in_sizes, int n_in,
                              void* d_out, int out_size)
{
    const float* coeffs  = (const float*)d_in[0];
    const float* times   = (const float*)d_in[1];
    const float* noise   = (const float*)d_in[2];
    const float* W_X     = (const float*)d_in[3];
    const float* b_X     = (const float*)d_in[4];
    const float* W_emb   = (const float*)d_in[5];
    const float* b_emb   = (const float*)d_in[6];
    const float* Wf1     = (const float*)d_in[7];
    const float* bf1     = (const float*)d_in[8];
    const float* Wf2     = (const float*)d_in[9];
    const float* bf2     = (const float*)d_in[10];
    const float* W_out   = (const float*)d_in[11];
    const float* b_out   = (const float*)d_in[12];
    const float* W_noise = (const float*)d_in[13];
    const float* b_noise = (const float*)d_in[14];
    const float* Wg1     = (const float*)d_in[15];
    const float* bg1     = (const float*)d_in[16];
    const float* Wg2     = (const float*)d_in[17];
    const float* bg2     = (const float*)d_in[18];
    const float* W_init  = (const float*)d_in[19];
    const float* b_init  = (const float*)d_in[20];
    const float* W_dec   = (const float*)d_in[21];
    const float* b_dec   = (const float*)d_in[22];
    const float* W_cls   = (const float*)d_in[23];
    const float* b_cls   = (const float*)d_in[24];
    const int*   mask    = (const int*)  d_in[25];
    float* out = (float*)d_out;

    float* pZ;
    cudaGetSymbolAddress((void**)&pZ, g_Z);

    cudaFuncSetAttribute(scan_kernel,
                         cudaFuncAttributeMaxDynamicSharedMemorySize, SMEM_BYTES);

    // 1. prep
    prep_kernel<<<(TSTEPS * HD + 255) / 256, 256>>>(times, W_noise, b_noise, mask);

    // 2. independent prolog GEMMs (one wide launch)
    stageA_kernel<<<1040, 256>>>(W_emb, Wf1, Wf2, W_out, b_out, Wg1, bg1,
                                 coeffs, W_init, b_init, bf2, b_emb, bf1);

    // 3. dependent prolog GEMMs (M, cvec, gt)
    stageB_kernel<<<160, 256>>>(W_X, b_X, Wg2, bg2);

    // 4. full 199-step scan (tensor cores, permuted-k smem, padded barriers)
    scan_kernel<<<RG * GROUP_CTAS, 256, SMEM_BYTES>>>(noise, coeffs);

    // 5. decode straight into (b,t,d) layout
    gemm_generic<<<dim3(2, 1600), 256>>>(pZ, HD, W_dec, DOUT, b_dec, 0,
                                         out, DOUT, TTOT * BSZ, DOUT, HD,
                                         ACT_DECODE);

    // 6. classifier logits
    cls_kernel<<<BSZ, 320>>>(W_cls, b_cls, out + (size_t)TTOT * BSZ * DOUT);
}

// round 17
// speedup vs baseline: 7.3030x; 1.3370x over previous
#include <cuda_runtime.h>
#include <cuda_bf16.h>
#include <math.h>

// Problem constants
#define TSTEPS 199
#define TTOT   200
#define BSZ    256
#define HD     512
#define BH     (BSZ*HD)        // 131072
#define DIN    64
#define DOUT   64
#define NCLS   10
#define LIPC   0.909f

#define ACT_NONE   0
#define ACT_LIP    1
#define ACT_DECODE 2

#define RG         8    // row groups (32 rows each)
#define GROUP_CTAS 16   // col CTAs per group (32 cols each)

// bf16 permuted-k layout: half k at p(k) = ((k>>1)&3)*144 + (k>>5)*8 + ((k>>3)&3)*2 + (k&1)
// row stride 584 halves = 1168 bytes = 73*16  -> LDS.128 phases conflict-free
#define RSTR_H 584
#define RSTR_B 1168
#define SMEM_BYTES (3*32*RSTR_B)      // sWy + sWo + sA = 112128 bytes

// ---------------- scratch (static device globals; no allocation) ----------------
__device__ __align__(256) float g_Z[TTOT*BH];              // trajectory   ~105MB
__device__ __align__(256) float g_h[BH];
__device__ __align__(256) float g_Wyf[HD*HD];              // W_emb_y @ Wf1
__device__ __align__(256) float g_W2o[HD*HD];              // Wf2 @ W_out
__device__ __align__(256) float g_E[HD*HD];                // W_emb_x @ Wf1
__device__ __align__(256) float g_b2o[HD];                 // bf2 @ W_out + b_out
__device__ __align__(256) float g_bvec1[HD];               // b_emb @ Wf1 + bf1
__device__ __align__(256) float g_M[DIN*HD];               // W_X @ E
__device__ __align__(256) float g_tt[TSTEPS*HD];
__device__ __align__(256) float g_G1[TSTEPS*HD];
__device__ __align__(256) float g_gt[TSTEPS*HD];
__device__ __align__(256) float g_cvec[HD];
__device__ float g_dts[TSTEPS];
__device__ float g_sqdts[TSTEPS];
__device__ int   g_lastidx[BSZ];
__device__ __align__(256) unsigned g_barctr[RG*32];        // 128B stride per group

__device__ __forceinline__ float lipswish(float x) {
    return LIPC * x / (1.0f + __expf(-x));
}

// half position within a permuted row
__device__ __forceinline__ int halfpos(int k) {
    return ((k >> 1) & 3) * 144 + ((k >> 5) << 3) + (((k >> 3) & 3) << 1) + (k & 1);
}
// u32 index of bf16x2 pair m (= halfpos(2m)/2)
__device__ __forceinline__ int pairidx(int m) {
    return ((m & 3) * 144 + ((m >> 4) << 3) + (((m >> 2) & 3) << 1)) >> 1;
}
__device__ __forceinline__ unsigned packbf2(float lo, float hi) {
    __nv_bfloat162 p = __floats2bfloat162_rn(lo, hi);   // x=lo, y=hi
    return *(unsigned*)&p;
}

// m16n8k16 bf16 MMA (row-major A, col-major B, fp32 accumulate)
__device__ __forceinline__ void mma_bf16(float& c0, float& c1, float& c2, float& c3,
                                         unsigned a0, unsigned a1, unsigned a2, unsigned a3,
                                         unsigned b0, unsigned b1)
{
    asm volatile(
        "mma.sync.aligned.m16n8k16.row.col.f32.bf16.bf16.f32 "
        "{%0,%1,%2,%3},{%4,%5,%6,%7},{%8,%9},{%0,%1,%2,%3};"
        : "+f"(c0), "+f"(c1), "+f"(c2), "+f"(c3)
        : "r"(a0), "r"(a1), "r"(a2), "r"(a3), "r"(b0), "r"(b1));
}

// ---------------- prep ----------------
__global__ void prep_kernel(const float* __restrict__ times,
                            const float* __restrict__ W_noise,
                            const float* __restrict__ b_noise,
                            const int*   __restrict__ mask)
{
    int idx = blockIdx.x * blockDim.x + threadIdx.x;
    if (idx < TSTEPS * HD) {
        int t = idx >> 9, h = idx & (HD - 1);
        g_tt[idx] = times[t] * W_noise[h] + b_noise[h];
    }
    if (idx < TSTEPS) {
        float d = times[idx + 1] - times[idx];
        g_dts[idx] = d;
        g_sqdts[idx] = sqrtf(d);
    }
    if (idx < BSZ) {
        int s = 0;
        for (int t = 0; t < TTOT; t++) s += mask[idx * TTOT + t];
        int li = s - 1;
        if (li < 0) li = 0;
        if (li > TTOT - 1) li = TTOT - 1;
        g_lastidx[idx] = li;
    }
    if (idx < RG * 32) g_barctr[idx] = 0u;
}

// ---------------- 32x32 GEMM tile device function ----------------------------
__device__ __forceinline__
void gemm_tile(const float* __restrict__ A, int lda,
               const float* __restrict__ B, int ldb,
               const float* __restrict__ bias, int bias_stride,
               float* __restrict__ C, int ldc,
               int M, int N, int K, int act, int tileX, int tileY,
               float As[32][33], float Bs[32][33])
{
    int tid = threadIdx.x;
    int tx = tid & 15, ty = tid >> 4;
    int rowBase = tileY * 32;
    int colBase = tileX * 32;

    float acc00 = 0.f, acc01 = 0.f, acc10 = 0.f, acc11 = 0.f;

    for (int k0 = 0; k0 < K; k0 += 32) {
        #pragma unroll
        for (int i = 0; i < 4; i++) {
            int idx = tid + i * 256;
            int r = idx >> 5, c = idx & 31;
            int ar = rowBase + r, ac = k0 + c;
            As[r][c] = (ar < M && ac < K) ? A[(size_t)ar * lda + ac] : 0.f;
            int br = k0 + r, bc = colBase + c;
            Bs[r][c] = (br < K && bc < N) ? B[(size_t)br * ldb + bc] : 0.f;
        }
        __syncthreads();
        #pragma unroll
        for (int kk = 0; kk < 32; kk++) {
            float a0 = As[ty][kk], a1 = As[ty + 16][kk];
            float b0 = Bs[kk][tx], b1 = Bs[kk][tx + 16];
            acc00 = fmaf(a0, b0, acc00);
            acc01 = fmaf(a0, b1, acc01);
            acc10 = fmaf(a1, b0, acc10);
            acc11 = fmaf(a1, b1, acc11);
        }
        __syncthreads();
    }

    int r0 = rowBase + ty, r1 = r0 + 16;
    int c0 = colBase + tx, c1 = c0 + 16;

    #pragma unroll
    for (int i = 0; i < 4; i++) {
        int r = (i & 2) ? r1 : r0;
        int c = (i & 1) ? c1 : c0;
        float v = (i == 0) ? acc00 : (i == 1) ? acc01 : (i == 2) ? acc10 : acc11;
        if (r < M && c < N) {
            if (bias) v += bias[(size_t)r * bias_stride + c];
            if (act == ACT_LIP) v = lipswish(v);
            if (act == ACT_DECODE) {
                C[((size_t)(r & 255) * TTOT + (r >> 8)) * DOUT + c] = v;
            } else {
                C[(size_t)r * ldc + c] = v;
            }
        }
    }
}

__global__ void gemm_generic(const float* __restrict__ A, int lda,
                             const float* __restrict__ B, int ldb,
                             const float* __restrict__ bias, int bias_stride,
                             float* __restrict__ C, int ldc,
                             int M, int N, int K, int act)
{
    __shared__ float As[32][33];
    __shared__ float Bs[32][33];
    gemm_tile(A, lda, B, ldb, bias, bias_stride, C, ldc, M, N, K, act,
              blockIdx.x, blockIdx.y, As, Bs);
}

// ---------------- stage A: all independent prolog GEMMs in one launch --------
__global__ void stageA_kernel(const float* __restrict__ W_emb,
                              const float* __restrict__ Wf1,
                              const float* __restrict__ Wf2,
                              const float* __restrict__ W_out,
                              const float* __restrict__ b_out,
                              const float* __restrict__ Wg1,
                              const float* __restrict__ bg1,
                              const float* __restrict__ coeffs,
                              const float* __restrict__ W_init,
                              const float* __restrict__ b_init,
                              const float* __restrict__ bf2,
                              const float* __restrict__ b_emb,
                              const float* __restrict__ bf1)
{
    __shared__ float As[32][33];
    __shared__ float Bs[32][33];
    int b = blockIdx.x;
    if (b < 256) {
        gemm_tile(W_emb, HD, Wf1, HD, nullptr, 0, g_Wyf, HD,
                  HD, HD, HD, ACT_NONE, b & 15, b >> 4, As, Bs);
    } else if (b < 512) {
        int l = b - 256;
        gemm_tile(W_emb + (size_t)HD * HD, HD, Wf1, HD, nullptr, 0, g_E, HD,
                  HD, HD, HD, ACT_NONE, l & 15, l >> 4, As, Bs);
    } else if (b < 768) {
        int l = b - 512;
        gemm_tile(Wf2, HD, W_out, HD, nullptr, 0, g_W2o, HD,
                  HD, HD, HD, ACT_NONE, l & 15, l >> 4, As, Bs);
    } else if (b < 880) {
        int l = b - 768;
        gemm_tile(g_tt, HD, Wg1, HD, bg1, 0, g_G1, HD,
                  TSTEPS, HD, HD, ACT_LIP, l & 15, l >> 4, As, Bs);
    } else if (b < 1008) {
        int l = b - 880;
        gemm_tile(coeffs, TSTEPS * 256, W_init, HD, b_init, 0, g_Z, HD,
                  BSZ, HD, DIN, ACT_NONE, l & 15, l >> 4, As, Bs);
    } else if (b < 1024) {
        int l = b - 1008;
        gemm_tile(bf2, HD, W_out, HD, b_out, 0, g_b2o, HD,
                  1, HD, HD, ACT_NONE, l, 0, As, Bs);
    } else {
        int l = b - 1024;
        gemm_tile(b_emb, HD, Wf1, HD, bf1, 0, g_bvec1, HD,
                  1, HD, HD, ACT_NONE, l, 0, As, Bs);
    }
}

// ---------------- stage B: dependent prolog GEMMs ----------------------------
__global__ void stageB_kernel(const float* __restrict__ W_X,
                              const float* __restrict__ b_X,
                              const float* __restrict__ Wg2,
                              const float* __restrict__ bg2)
{
    __shared__ float As[32][33];
    __shared__ float Bs[32][33];
    int b = blockIdx.x;
    if (b < 32) {
        gemm_tile(W_X, HD, g_E, HD, nullptr, 0, g_M, HD,
                  DIN, HD, HD, ACT_NONE, b & 15, b >> 4, As, Bs);
    } else if (b < 48) {
        int l = b - 32;
        gemm_tile(b_X, HD, g_E, HD, g_bvec1, 0, g_cvec, HD,
                  1, HD, HD, ACT_NONE, l, 0, As, Bs);
    } else {
        int l = b - 48;
        gemm_tile(g_G1, HD, Wg2, HD, bg2, 0, g_gt, HD,
                  TSTEPS, HD, HD, ACT_NONE, l & 15, l >> 4, As, Bs);
    }
}

// ---------------- group-local barrier (padded counters) ----------------------
__device__ __forceinline__ void group_barrier(int g, unsigned target)
{
    __syncthreads();
    if (threadIdx.x == 0) {
        unsigned* ctr = &g_barctr[g * 32];
        asm volatile("red.release.gpu.global.add.u32 [%0], 1;"
                     :: "l"(ctr) : "memory");
        unsigned v;
        do {
            asm volatile("ld.acquire.gpu.global.u32 %0, [%1];"
                         : "=r"(v) : "l"(ctr) : "memory");
        } while (v < target);
    }
    __syncthreads();
}

// ---------------- persistent scan kernel (bf16 m16n8k16 tensor cores) --------
// GEMM1: h = lipswish([y ; a_t] @ [Wyf ; M] + cvec)   (K = 576, 36 MMAs)
// GEMM2: y' = y + (h @ W2o + b2o)*dt + gt*noise*sqdt  (K = 512, 32 MMAs)
__global__ void __launch_bounds__(256, 1)
scan_kernel(const float* __restrict__ noise, const float* __restrict__ coeffs)
{
    extern __shared__ __align__(16) char smemraw[];
    __nv_bfloat16* sWy = (__nv_bfloat16*)smemraw;        // 32 cols x RSTR_H
    __nv_bfloat16* sWo = sWy + 32 * RSTR_H;
    __nv_bfloat16* sA  = sWo + 32 * RSTR_H;              // 32 rows x RSTR_H

    const int g    = blockIdx.x >> 4;
    const int c0   = (blockIdx.x & 15) << 5;
    const int r0   = g << 5;
    const int tid  = threadIdx.x;
    const int lane = tid & 31;
    const int w    = tid >> 5;
    const int wrow = w & 1;
    const int wcol = w >> 1;
    const int gq   = lane >> 2;
    const int t4   = lane & 3;

    const int lrA = wrow * 16 + gq;
    const int lrB = lrA + 8;
    const int lcB = wcol * 8 + gq;
    const int rA = r0 + lrA, rB = r0 + lrB;
    const int cA = c0 + wcol * 8 + 2 * t4;

    // ---- persistent weights: transpose + permute + bf16 (once) ----
    {
        int col = tid & 31;
        int kb  = tid >> 5;
        #pragma unroll 4
        for (int it = 0; it < 64; it++) {
            int k = kb + (it << 3);
            int p = halfpos(k);
            sWy[col * RSTR_H + p] = __float2bfloat16(g_Wyf[(size_t)k * HD + c0 + col]);
            sWo[col * RSTR_H + p] = __float2bfloat16(g_W2o[(size_t)k * HD + c0 + col]);
        }
        #pragma unroll
        for (int it = 0; it < 8; it++) {
            int km = kb + (it << 3);
            sWy[col * RSTR_H + halfpos(512 + km)] =
                __float2bfloat16(g_M[(size_t)km * HD + c0 + col]);
        }
    }

    const float2 cv = *(const float2*)(g_cvec + cA);
    const float2 b2 = *(const float2*)(g_b2o + cA);

    const uint4* a0p = (const uint4*)((const char*)sA + lrA * RSTR_B + t4 * 288);
    const uint4* a1p = (const uint4*)((const char*)sA + lrB * RSTR_B + t4 * 288);
    const uint4* byp = (const uint4*)((const char*)sWy + lcB * RSTR_B + t4 * 288);
    const uint4* bop = (const uint4*)((const char*)sWo + lcB * RSTR_B + t4 * 288);

    unsigned target = GROUP_CTAS;

    for (int t = 0; t < TSTEPS; t++) {
        const float* Zt = g_Z + (size_t)t * BH;
        float*       Zn = g_Z + (size_t)(t + 1) * BH;

        // ---- fill A: y rows (bf16x2 permuted scatter) + a_t block ----
        {
            const float* src = Zt + (size_t)r0 * HD;
            #pragma unroll 4
            for (int it = 0; it < 16; it++) {
                int f4 = tid + (it << 8);
                int row = f4 >> 7, q = f4 & 127;       // k = 4q .. 4q+3
                float4 v = *(const float4*)(src + (size_t)row * HD + (q << 2));
                unsigned* d = (unsigned*)((char*)sA + row * RSTR_B);
                d[pairidx(2 * q)]     = packbf2(v.x, v.y);
                d[pairidx(2 * q + 1)] = packbf2(v.z, v.w);
            }
            #pragma unroll
            for (int it = 0; it < 2; it++) {
                int f4 = tid + (it << 8);
                int row = f4 >> 4, qq = f4 & 15;       // k = 512 + 4qq
                float4 v = *(const float4*)(coeffs +
                            ((size_t)(r0 + row) * TSTEPS + t) * 256 + (qq << 2));
                unsigned* d = (unsigned*)((char*)sA + row * RSTR_B);
                int q = 128 + qq;
                d[pairidx(2 * q)]     = packbf2(v.x, v.y);
                d[pairidx(2 * q + 1)] = packbf2(v.z, v.w);
            }
        }
        __syncthreads();

        // ---- GEMM1: 36 MMAs (18 pairs), 4 accumulator chains ----
        float u0 = 0.f, u1 = 0.f, u2 = 0.f, u3 = 0.f;
        float v0 = 0.f, v1 = 0.f, v2 = 0.f, v3 = 0.f;
        float x0 = 0.f, x1 = 0.f, x2 = 0.f, x3 = 0.f;
        float y0 = 0.f, y1 = 0.f, y2 = 0.f, y3 = 0.f;
        {
            #pragma unroll
            for (int i = 0; i < 18; i += 2) {
                uint4 AL0 = a0p[i],     AH0 = a1p[i],     B0 = byp[i];
                uint4 AL1 = a0p[i + 1], AH1 = a1p[i + 1], B1 = byp[i + 1];
                mma_bf16(u0, u1, u2, u3, AL0.x, AH0.x, AL0.y, AH0.y, B0.x, B0.y);
                mma_bf16(v0, v1, v2, v3, AL0.z, AH0.z, AL0.w, AH0.w, B0.z, B0.w);
                mma_bf16(x0, x1, x2, x3, AL1.x, AH1.x, AL1.y, AH1.y, B1.x, B1.y);
                mma_bf16(y0, y1, y2, y3, AL1.z, AH1.z, AL1.w, AH1.w, B1.z, B1.w);
            }
        }
        {
            float d0 = (u0 + v0) + (x0 + y0);
            float d1 = (u1 + v1) + (x1 + y1);
            float d2 = (u2 + v2) + (x2 + y2);
            float d3 = (u3 + v3) + (x3 + y3);
            float2 h0, h1;
            h0.x = lipswish(d0 + cv.x); h0.y = lipswish(d1 + cv.y);
            h1.x = lipswish(d2 + cv.x); h1.y = lipswish(d3 + cv.y);
            *(float2*)(g_h + (size_t)rA * HD + cA) = h0;
            *(float2*)(g_h + (size_t)rB * HD + cA) = h1;
        }

        // prefetch GEMM2 epilogue operands BEFORE the barrier
        const float dt = g_dts[t], sq = g_sqdts[t];
        float2 gt2 = *(const float2*)(g_gt + t * HD + cA);
        const float* Nt = noise + (size_t)t * BH;
        float2 nA = *(const float2*)(Nt + (size_t)rA * HD + cA);
        float2 nB = *(const float2*)(Nt + (size_t)rB * HD + cA);
        float2 zA = *(const float2*)(Zt + (size_t)rA * HD + cA);
        float2 zB = *(const float2*)(Zt + (size_t)rB * HD + cA);

        group_barrier(g, target); target += GROUP_CTAS;

        // ---- fill A = h (bf16x2 permuted scatter) ----
        {
            const float* src = g_h + (size_t)r0 * HD;
            #pragma unroll 4
            for (int it = 0; it < 16; it++) {
                int f4 = tid + (it << 8);
                int row = f4 >> 7, q = f4 & 127;
                float4 v = *(const float4*)(src + (size_t)row * HD + (q << 2));
                unsigned* d = (unsigned*)((char*)sA + row * RSTR_B);
                d[pairidx(2 * q)]     = packbf2(v.x, v.y);
                d[pairidx(2 * q + 1)] = packbf2(v.z, v.w);
            }
        }
        __syncthreads();

        // ---- GEMM2: 32 MMAs (16 pairs) ----
        u0 = u1 = u2 = u3 = 0.f;
        v0 = v1 = v2 = v3 = 0.f;
        x0 = x1 = x2 = x3 = 0.f;
        y0 = y1 = y2 = y3 = 0.f;
        {
            #pragma unroll
            for (int i = 0; i < 16; i += 2) {
                uint4 AL0 = a0p[i],     AH0 = a1p[i],     B0 = bop[i];
                uint4 AL1 = a0p[i + 1], AH1 = a1p[i + 1], B1 = bop[i + 1];
                mma_bf16(u0, u1, u2, u3, AL0.x, AH0.x, AL0.y, AH0.y, B0.x, B0.y);
                mma_bf16(v0, v1, v2, v3, AL0.z, AH0.z, AL0.w, AH0.w, B0.z, B0.w);
                mma_bf16(x0, x1, x2, x3, AL1.x, AH1.x, AL1.y, AH1.y, B1.x, B1.y);
                mma_bf16(y0, y1, y2, y3, AL1.z, AH1.z, AL1.w, AH1.w, B1.z, B1.w);
            }
        }
        {
            float d0 = (u0 + v0) + (x0 + y0);
            float d1 = (u1 + v1) + (x1 + y1);
            float d2 = (u2 + v2) + (x2 + y2);
            float d3 = (u3 + v3) + (x3 + y3);
            float gx = gt2.x * sq, gy = gt2.y * sq;
            float2 w0, w1;
            w0.x = zA.x + (d0 + b2.x) * dt + gx * nA.x;
            w0.y = zA.y + (d1 + b2.y) * dt + gy * nA.y;
            w1.x = zB.x + (d2 + b2.x) * dt + gx * nB.x;
            w1.y = zB.y + (d3 + b2.y) * dt + gy * nB.y;
            *(float2*)(Zn + (size_t)rA * HD + cA) = w0;
            *(float2*)(Zn + (size_t)rB * HD + cA) = w1;
        }
        group_barrier(g, target); target += GROUP_CTAS;
    }
}

// ---------------- classifier ----------------
__global__ void cls_kernel(const float* __restrict__ W_cls,
                           const float* __restrict__ b_cls,
                           float* __restrict__ logits)
{
    int b = blockIdx.x;
    int w = threadIdx.x >> 5, lane = threadIdx.x & 31;
    if (w >= NCLS) return;
    int li = g_lastidx[b];
    const float* z = g_Z + ((size_t)li * BSZ + b) * HD;
    float s = 0.f;
    for (int h = lane; h < HD; h += 32)
        s += z[h] * W_cls[h * NCLS + w];
    #pragma unroll
    for (int o = 16; o; o >>= 1) s += __shfl_down_sync(0xffffffffu, s, o);
    if (lane == 0) logits[b * NCLS + w] = s + b_cls[w];
}

// ---------------- launch ----------------
extern "C" void kernel_launch(void* const* d_in, const int* in_sizes, int n_in,
                              void* d_out, int out_size)
{
    const float* coeffs  = (const float*)d_in[0];
    const float* times   = (const float*)d_in[1];
    const float* noise   = (const float*)d_in[2];
    const float* W_X     = (const float*)d_in[3];
    const float* b_X     = (const float*)d_in[4];
    const float* W_emb   = (const float*)d_in[5];
    const float* b_emb   = (const float*)d_in[6];
    const float* Wf1     = (const float*)d_in[7];
    const float* bf1     = (const float*)d_in[8];
    const float* Wf2     = (const float*)d_in[9];
    const float* bf2     = (const float*)d_in[10];
    const float* W_out   = (const float*)d_in[11];
    const float* b_out   = (const float*)d_in[12];
    const float* W_noise = (const float*)d_in[13];
    const float* b_noise = (const float*)d_in[14];
    const float* Wg1     = (const float*)d_in[15];
    const float* bg1     = (const float*)d_in[16];
    const float* Wg2     = (const float*)d_in[17];
    const float* bg2     = (const float*)d_in[18];
    const float* W_init  = (const float*)d_in[19];
    const float* b_init  = (const float*)d_in[20];
    const float* W_dec   = (const float*)d_in[21];
    const float* b_dec   = (const float*)d_in[22];
    const float* W_cls   = (const float*)d_in[23];
    const float* b_cls   = (const float*)d_in[24];
    const int*   mask    = (const int*)  d_in[25];
    float* out = (float*)d_out;

    float* pZ;
    cudaGetSymbolAddress((void**)&pZ, g_Z);

    cudaFuncSetAttribute(scan_kernel,
                         cudaFuncAttributeMaxDynamicSharedMemorySize, SMEM_BYTES);

    // 1. prep
    prep_kernel<<<(TSTEPS * HD + 255) / 256, 256>>>(times, W_noise, b_noise, mask);

    // 2. independent prolog GEMMs (one wide launch)
    stageA_kernel<<<1040, 256>>>(W_emb, Wf1, Wf2, W_out, b_out, Wg1, bg1,
                                 coeffs, W_init, b_init, bf2, b_emb, bf1);

    // 3. dependent prolog GEMMs (M, cvec, gt)
    stageB_kernel<<<160, 256>>>(W_X, b_X, Wg2, bg2);

    // 4. full 199-step scan (bf16 m16n8k16 tensor cores, permuted-k smem)
    scan_kernel<<<RG * GROUP_CTAS, 256, SMEM_BYTES>>>(noise, coeffs);

    // 5. decode straight into (b,t,d) layout
    gemm_generic<<<dim3(2, 1600), 256>>>(pZ, HD, W_dec, DOUT, b_dec, 0,
                                         out, DOUT, TTOT * BSZ, DOUT, HD,
                                         ACT_DECODE);

    // 6. classifier logits
    cls_kernel<<<BSZ, 320>>>(W_cls, b_cls, out + (size_t)TTOT * BSZ * DOUT);
}